// round 2
// baseline (speedup 1.0000x reference)
#include <cuda_runtime.h>
#include <cuda_bf16.h>
#include <math.h>

#define BB 2
#define LL 4096
#define DD 1024
#define DIN 2048
#define DSTATE 128
#define NH 32
#define HD 64
#define CONVDIM 2304
#define DPROJ 4384
#define NCHUNK 8
#define CHL (LL / NCHUNK)

// ---------------- scratch (device globals; no allocation allowed) ----------------
__device__ float g_xn[BB * LL * DD];          // rmsnorm(x)
__device__ float g_zx[BB * LL * DPROJ];       // xn @ in_proj_W
__device__ float g_conv[BB * LL * CONVDIM];   // silu(conv1d(xBC))
__device__ float g_dt[BB * LL * NH];          // softplus(dt + bias)
__device__ float g_dA[BB * LL * NH];          // exp(dt * A)
__device__ float g_y[BB * LL * DIN];          // mamba inner output (then gated-normed in place)
__device__ float g_P[BB * LL * DD];           // xn @ Wz
__device__ float g_Q[BB * LL * DD];           // xn @ Wc   (to be cumsummed)
__device__ float g_R[BB * LL * DD];           // y  @ Fm
__device__ float g_Wz[DD * DD];               // zero_W @ fusion_W[2048:4096]
__device__ float g_Wc[DD * DD];               // one_W  @ fusion_W[4096:6144]
__device__ float g_cs[BB * NCHUNK * DD];      // cumsum chunk offsets

// ---------------- helpers ----------------
__inline__ __device__ float blockReduceSum(float v) {
    __shared__ float sh[32];
    int lane = threadIdx.x & 31, wid = threadIdx.x >> 5;
#pragma unroll
    for (int o = 16; o > 0; o >>= 1) v += __shfl_down_sync(0xffffffffu, v, o);
    if (lane == 0) sh[wid] = v;
    __syncthreads();
    v = (threadIdx.x < (blockDim.x >> 5)) ? sh[lane] : 0.f;
    if (wid == 0) {
#pragma unroll
        for (int o = 16; o > 0; o >>= 1) v += __shfl_down_sync(0xffffffffu, v, o);
        if (lane == 0) sh[0] = v;
    }
    __syncthreads();
    return sh[0];
}

__inline__ __device__ float siluf(float v) { return v / (1.f + expf(-v)); }

// ---------------- rmsnorm (x -> xn) ----------------
__global__ void rmsnorm_kernel(const float* __restrict__ x, const float* __restrict__ w,
                               float* __restrict__ out) {
    size_t row = blockIdx.x;
    const float* xr = x + row * DD;
    float ss = 0.f;
    for (int i = threadIdx.x; i < DD; i += blockDim.x) { float v = xr[i]; ss += v * v; }
    ss = blockReduceSum(ss);
    float inv = rsqrtf(ss / (float)DD + 1e-5f);
    float* o = out + row * DD;
    for (int i = threadIdx.x; i < DD; i += blockDim.x) o[i] = xr[i] * inv * w[i];
}

// ---------------- fp32 SGEMM: C[M,N] = A[M,K] @ B[K,N] (row-major) ----------------
// 128x128 tile, 256 threads, 8x8 per thread. Requires K%8==0, N%4==0.
__global__ __launch_bounds__(256, 2) void sgemm_kernel(const float* __restrict__ A,
                                                       const float* __restrict__ Bm,
                                                       float* __restrict__ C,
                                                       int M, int N, int K) {
    __shared__ __align__(16) float As[8][128];
    __shared__ __align__(16) float Bs[8][128];
    int t = threadIdx.x;
    int tx = t & 15, ty = t >> 4;
    int m0 = blockIdx.y * 128, n0 = blockIdx.x * 128;
    int arow = t >> 1;
    int akq = (t & 1) * 4;
    int brow = t >> 5;
    int bcol = (t & 31) * 4;

    float acc[8][8];
#pragma unroll
    for (int i = 0; i < 8; i++)
#pragma unroll
        for (int j = 0; j < 8; j++) acc[i][j] = 0.f;

    for (int k0 = 0; k0 < K; k0 += 8) {
        float4 av = make_float4(0.f, 0.f, 0.f, 0.f);
        if (m0 + arow < M)
            av = *reinterpret_cast<const float4*>(&A[(size_t)(m0 + arow) * K + k0 + akq]);
        As[akq + 0][arow] = av.x;
        As[akq + 1][arow] = av.y;
        As[akq + 2][arow] = av.z;
        As[akq + 3][arow] = av.w;
        float4 bv = make_float4(0.f, 0.f, 0.f, 0.f);
        if (n0 + bcol < N)
            bv = *reinterpret_cast<const float4*>(&Bm[(size_t)(k0 + brow) * N + n0 + bcol]);
        *reinterpret_cast<float4*>(&Bs[brow][bcol]) = bv;
        __syncthreads();
#pragma unroll
        for (int kk = 0; kk < 8; kk++) {
            float a[8], bf[8];
            *reinterpret_cast<float4*>(&a[0]) = *reinterpret_cast<float4*>(&As[kk][ty * 4]);
            *reinterpret_cast<float4*>(&a[4]) = *reinterpret_cast<float4*>(&As[kk][64 + ty * 4]);
            *reinterpret_cast<float4*>(&bf[0]) = *reinterpret_cast<float4*>(&Bs[kk][tx * 4]);
            *reinterpret_cast<float4*>(&bf[4]) = *reinterpret_cast<float4*>(&Bs[kk][64 + tx * 4]);
#pragma unroll
            for (int i = 0; i < 8; i++)
#pragma unroll
                for (int j = 0; j < 8; j++) acc[i][j] += a[i] * bf[j];
        }
        __syncthreads();
    }
#pragma unroll
    for (int i = 0; i < 8; i++) {
        int m = m0 + ((i < 4) ? (ty * 4 + i) : (64 + ty * 4 + i - 4));
        if (m >= M) continue;
#pragma unroll
        for (int j = 0; j < 8; j++) {
            int n = n0 + ((j < 4) ? (tx * 4 + j) : (64 + tx * 4 + j - 4));
            if (n < N) C[(size_t)m * N + n] = acc[i][j];
        }
    }
}

// ---------------- causal conv1d + silu over xBC channels ----------------
__global__ void conv_kernel(const float* __restrict__ zx, const float* __restrict__ cw,
                            const float* __restrict__ cb, float* __restrict__ out) {
    size_t idx = (size_t)blockIdx.x * blockDim.x + threadIdx.x;
    if (idx >= (size_t)BB * LL * CONVDIM) return;
    int c = idx % CONVDIM;
    size_t rest = idx / CONVDIM;
    int t = rest % LL;
    int b = rest / LL;
    float acc = cb[c];
#pragma unroll
    for (int k = 0; k < 4; k++) {
        int tt = t - 3 + k;
        if (tt >= 0)
            acc += zx[((size_t)b * LL + tt) * DPROJ + DIN + c] * cw[k * CONVDIM + c];
    }
    out[idx] = siluf(acc);
}

// ---------------- dt softplus + dA ----------------
__global__ void dtda_kernel(const float* __restrict__ zx, const float* __restrict__ dtb,
                            const float* __restrict__ alog, float* __restrict__ dt,
                            float* __restrict__ dA) {
    size_t idx = (size_t)blockIdx.x * blockDim.x + threadIdx.x;
    if (idx >= (size_t)BB * LL * NH) return;
    int h = idx % NH;
    size_t row = idx / NH;
    float raw = zx[row * DPROJ + (DPROJ - NH) + h] + dtb[h];
    float sp = (raw > 20.f) ? raw : log1pf(expf(raw));
    dt[idx] = sp;
    dA[idx] = expf(sp * (-expf(alog[h])));
}

// ---------------- sequential SSM scan: one block per (b, head) ----------------
__global__ __launch_bounds__(1024, 1) void scan_kernel(const float* __restrict__ conv,
                                                       const float* __restrict__ dt,
                                                       const float* __restrict__ dA,
                                                       const float* __restrict__ Dp,
                                                       float* __restrict__ y) {
    int b = blockIdx.x >> 5;
    int h = blockIdx.x & 31;
    int tid = threadIdx.x;
    int p = tid >> 4;    // 0..63 (headdim)
    int ln = tid & 15;   // lane within 16-thread group
    __shared__ float sB[2][128], sC[2][128], sx[2][64];
    __shared__ float sdt[2], sdA[2];
    float S[8];
#pragma unroll
    for (int j = 0; j < 8; j++) S[j] = 0.f;
    float Dh = Dp[h];

    {   // preload t=0
        const float* row = conv + ((size_t)b * LL) * CONVDIM;
        if (tid < 128) sB[0][tid] = row[2048 + tid];
        else if (tid < 256) sC[0][tid - 128] = row[2176 + (tid - 128)];
        else if (tid < 320) sx[0][tid - 256] = row[h * HD + (tid - 256)];
        else if (tid == 320) {
            size_t o = ((size_t)b * LL) * NH + h;
            sdt[0] = dt[o]; sdA[0] = dA[o];
        }
    }
    for (int t = 0; t < LL; t++) {
        int cur = t & 1;
        __syncthreads();
        if (t + 1 < LL) {
            int nb = cur ^ 1;
            const float* row = conv + ((size_t)b * LL + t + 1) * CONVDIM;
            if (tid < 128) sB[nb][tid] = row[2048 + tid];
            else if (tid < 256) sC[nb][tid - 128] = row[2176 + (tid - 128)];
            else if (tid < 320) sx[nb][tid - 256] = row[h * HD + (tid - 256)];
            else if (tid == 320) {
                size_t o = ((size_t)b * LL + t + 1) * NH + h;
                sdt[nb] = dt[o]; sdA[nb] = dA[o];
            }
        }
        float xv = sx[cur][p];
        float dtx = sdt[cur] * xv;
        float a = sdA[cur];
        float part = 0.f;
#pragma unroll
        for (int j = 0; j < 8; j++) {
            int n = ln + 16 * j;
            S[j] = S[j] * a + dtx * sB[cur][n];
            part += S[j] * sC[cur][n];
        }
        part += __shfl_down_sync(0xffffffffu, part, 8, 16);
        part += __shfl_down_sync(0xffffffffu, part, 4, 16);
        part += __shfl_down_sync(0xffffffffu, part, 2, 16);
        part += __shfl_down_sync(0xffffffffu, part, 1, 16);
        if (ln == 0) y[((size_t)b * LL + t) * DIN + h * HD + p] = part + Dh * xv;
    }
}

// ---------------- gated rmsnorm: y = rmsnorm(y * silu(z), gnorm_w) ----------------
__global__ void gnorm_kernel(float* __restrict__ y, const float* __restrict__ zx,
                             const float* __restrict__ gw) {
    size_t row = blockIdx.x;
    float* yr = y + row * DIN;
    const float* zr = zx + row * DPROJ;
    float v[8];
    float ss = 0.f;
#pragma unroll
    for (int u = 0; u < 8; u++) {
        int i = threadIdx.x + u * 256;
        float z = zr[i];
        float val = yr[i] * siluf(z);
        v[u] = val;
        ss += val * val;
    }
    ss = blockReduceSum(ss);
    float inv = rsqrtf(ss / (float)DIN + 1e-5f);
#pragma unroll
    for (int u = 0; u < 8; u++) {
        int i = threadIdx.x + u * 256;
        yr[i] = v[u] * inv * gw[i];
    }
}

// ---------------- cumsum passes ----------------
__global__ void chunk_sum_kernel(const float* __restrict__ Q, float* __restrict__ cs) {
    int c = (blockIdx.x & 3) * 256 + threadIdx.x;
    int chunk = (blockIdx.x >> 2) & (NCHUNK - 1);
    int b = blockIdx.x >> 5;  // 2*NCHUNK*4 = 64 blocks; b = blk / 32
    float s = 0.f;
    size_t base = ((size_t)b * LL + (size_t)chunk * CHL) * DD + c;
    for (int l = 0; l < CHL; l++) s += Q[base + (size_t)l * DD];
    cs[((size_t)b * NCHUNK + chunk) * DD + c] = s;
}

__global__ void scan_chunks_kernel(float* __restrict__ cs) {
    int i = blockIdx.x * blockDim.x + threadIdx.x;
    if (i >= BB * DD) return;
    int b = i / DD, c = i % DD;
    float acc = 0.f;
#pragma unroll
    for (int ch = 0; ch < NCHUNK; ch++) {
        size_t o = ((size_t)b * NCHUNK + ch) * DD + c;
        float v = cs[o];
        cs[o] = acc;      // exclusive prefix
        acc += v;
    }
}

__global__ void final_kernel(const float* __restrict__ x, const float* __restrict__ P,
                             const float* __restrict__ R, const float* __restrict__ Q,
                             const float* __restrict__ cs, float* __restrict__ out) {
    int c = (blockIdx.x & 3) * 256 + threadIdx.x;
    int chunk = (blockIdx.x >> 2) & (NCHUNK - 1);
    int b = blockIdx.x >> 5;
    float acc = cs[((size_t)b * NCHUNK + chunk) * DD + c];
    size_t base = ((size_t)b * LL + (size_t)chunk * CHL) * DD + c;
    for (int l = 0; l < CHL; l++) {
        size_t idx = base + (size_t)l * DD;
        acc += Q[idx];
        out[idx] = x[idx] + P[idx] + R[idx] + acc;
    }
}

// ---------------- launch ----------------
extern "C" void kernel_launch(void* const* d_in, const int* in_sizes, int n_in,
                              void* d_out, int out_size) {
    const float* x       = (const float*)d_in[0];
    const float* norm_w  = (const float*)d_in[1];
    const float* in_proj = (const float*)d_in[2];
    const float* conv_W  = (const float*)d_in[3];
    const float* conv_b  = (const float*)d_in[4];
    const float* dt_bias = (const float*)d_in[5];
    const float* A_log   = (const float*)d_in[6];
    const float* Dvec    = (const float*)d_in[7];
    const float* gnorm_w = (const float*)d_in[8];
    const float* zero_W  = (const float*)d_in[9];
    const float* one_W   = (const float*)d_in[10];
    const float* fusion  = (const float*)d_in[11];
    float* out = (float*)d_out;

    float *xn, *zx, *conv, *dt, *dA, *y, *P, *Q, *R, *Wz, *Wc, *cs;
    cudaGetSymbolAddress((void**)&xn, g_xn);
    cudaGetSymbolAddress((void**)&zx, g_zx);
    cudaGetSymbolAddress((void**)&conv, g_conv);
    cudaGetSymbolAddress((void**)&dt, g_dt);
    cudaGetSymbolAddress((void**)&dA, g_dA);
    cudaGetSymbolAddress((void**)&y, g_y);
    cudaGetSymbolAddress((void**)&P, g_P);
    cudaGetSymbolAddress((void**)&Q, g_Q);
    cudaGetSymbolAddress((void**)&R, g_R);
    cudaGetSymbolAddress((void**)&Wz, g_Wz);
    cudaGetSymbolAddress((void**)&Wc, g_Wc);
    cudaGetSymbolAddress((void**)&cs, g_cs);

    const int M = BB * LL;  // 8192 rows

    // 1. xn = rmsnorm(x)
    rmsnorm_kernel<<<M, 256>>>(x, norm_w, xn);

    // 2. zx = xn @ in_proj_W   (8192 x 1024 x 4384)
    {
        dim3 grid((DPROJ + 127) / 128, (M + 127) / 128);
        sgemm_kernel<<<grid, 256>>>(xn, in_proj, zx, M, DPROJ, DD);
    }

    // 3. combined weights: Wz = zero_W @ Fz, Wc = one_W @ Fo
    {
        dim3 grid((DD + 127) / 128, (DD + 127) / 128);
        sgemm_kernel<<<grid, 256>>>(zero_W, fusion + (size_t)DIN * DD, Wz, DD, DD, DIN);
        sgemm_kernel<<<grid, 256>>>(one_W, fusion + (size_t)2 * DIN * DD, Wc, DD, DD, DIN);
    }

    // 4. P = xn @ Wz ; Q = xn @ Wc   (8192 x 1024 x 1024 each)
    {
        dim3 grid((DD + 127) / 128, (M + 127) / 128);
        sgemm_kernel<<<grid, 256>>>(xn, Wz, P, M, DD, DD);
        sgemm_kernel<<<grid, 256>>>(xn, Wc, Q, M, DD, DD);
    }

    // 5. conv + silu
    {
        size_t tot = (size_t)BB * LL * CONVDIM;
        conv_kernel<<<(unsigned)((tot + 255) / 256), 256>>>(zx, conv_W, conv_b, conv);
    }

    // 6. dt / dA
    {
        size_t tot = (size_t)BB * LL * NH;
        dtda_kernel<<<(unsigned)((tot + 255) / 256), 256>>>(zx, dt_bias, A_log, dt, dA);
    }

    // 7. SSM scan
    scan_kernel<<<BB * NH, 1024>>>(conv, dt, dA, Dvec, y);

    // 8. gated rmsnorm (in place on y)
    gnorm_kernel<<<M, 256>>>(y, zx, gnorm_w);

    // 9. R = y @ Fm   (8192 x 2048 x 1024)
    {
        dim3 grid((DD + 127) / 128, (M + 127) / 128);
        sgemm_kernel<<<grid, 256>>>(y, fusion, R, M, DD, DIN);
    }

    // 10. cumsum of Q along l, fused with final add
    chunk_sum_kernel<<<BB * NCHUNK * 4, 256>>>(Q, cs);
    scan_chunks_kernel<<<(BB * DD + 255) / 256, 256>>>(cs);
    final_kernel<<<BB * NCHUNK * 4, 256>>>(x, P, R, Q, cs, out);
}

// round 4
// speedup vs baseline: 1.4777x; 1.4777x over previous
#include <cuda_runtime.h>
#include <cuda_bf16.h>
#include <math.h>
#include <stdint.h>

#define BB 2
#define LL 4096
#define DD 1024
#define DIN 2048
#define DSTATE 128
#define NH 32
#define HD 64
#define CONVDIM 2304
#define DPROJ 4384
#define NPADPROJ 4480
#define NCHUNK 8
#define CHL (LL / NCHUNK)

// ---------------- scratch (device globals) ----------------
__device__ float g_zx[BB * LL * DPROJ];
__device__ float g_conv[BB * LL * CONVDIM];
__device__ float g_dt[BB * LL * NH];
__device__ float g_dA[BB * LL * NH];
__device__ float g_y[BB * LL * DIN];
__device__ float g_P[BB * LL * DD];
__device__ float g_Q[BB * LL * DD];
__device__ float g_R[BB * LL * DD];
__device__ float g_Wz[DD * DD];
__device__ float g_Wc[DD * DD];
__device__ float g_cs[BB * NCHUNK * DD];

__device__ __nv_bfloat16 g_xnh[BB * LL * DD], g_xnl[BB * LL * DD];
__device__ __nv_bfloat16 g_Wpth[NPADPROJ * DD], g_Wptl[NPADPROJ * DD];
__device__ __nv_bfloat16 g_Fzth[DD * DIN], g_Fztl[DD * DIN];
__device__ __nv_bfloat16 g_Foth[DD * DIN], g_Fotl[DD * DIN];
__device__ __nv_bfloat16 g_Fmth[DD * DIN], g_Fmtl[DD * DIN];
__device__ __nv_bfloat16 g_zwh[DD * DIN], g_zwl[DD * DIN];
__device__ __nv_bfloat16 g_owh[DD * DIN], g_owl[DD * DIN];
__device__ __nv_bfloat16 g_Wzth[DD * DD], g_Wztl[DD * DD];
__device__ __nv_bfloat16 g_Wcth[DD * DD], g_Wctl[DD * DD];
__device__ __nv_bfloat16 g_yh[BB * LL * DIN], g_yl[BB * LL * DIN];

// ---------------- helpers ----------------
__device__ __forceinline__ uint32_t s2u(const void* p) {
    uint32_t a;
    asm("{ .reg .u64 t; cvta.to.shared.u64 t, %1; cvt.u32.u64 %0, t; }" : "=r"(a) : "l"(p));
    return a;
}

#define LDSM4(r0, r1, r2, r3, addr)                                                         \
    asm volatile("ldmatrix.sync.aligned.m8n8.x4.shared.b16 {%0,%1,%2,%3}, [%4];"            \
                 : "=r"(r0), "=r"(r1), "=r"(r2), "=r"(r3) : "r"(addr))

#define MMA16816(c, a, b)                                                                   \
    asm volatile("mma.sync.aligned.m16n8k16.row.col.f32.bf16.bf16.f32 "                     \
                 "{%0,%1,%2,%3}, {%4,%5,%6,%7}, {%8,%9}, {%0,%1,%2,%3};"                    \
                 : "+f"((c)[0]), "+f"((c)[1]), "+f"((c)[2]), "+f"((c)[3])                   \
                 : "r"((a)[0]), "r"((a)[1]), "r"((a)[2]), "r"((a)[3]),                      \
                   "r"((b)[0]), "r"((b)[1]))

__device__ __forceinline__ void split_bf16(float v, __nv_bfloat16& h, __nv_bfloat16& l) {
    h = __float2bfloat16(v);
    l = __float2bfloat16(v - __bfloat162float(h));
}

__inline__ __device__ float blockReduceSum(float v) {
    __shared__ float sh[32];
    int lane = threadIdx.x & 31, wid = threadIdx.x >> 5;
#pragma unroll
    for (int o = 16; o > 0; o >>= 1) v += __shfl_down_sync(0xffffffffu, v, o);
    if (lane == 0) sh[wid] = v;
    __syncthreads();
    v = (threadIdx.x < (blockDim.x >> 5)) ? sh[lane] : 0.f;
    if (wid == 0) {
#pragma unroll
        for (int o = 16; o > 0; o >>= 1) v += __shfl_down_sync(0xffffffffu, v, o);
        if (lane == 0) sh[0] = v;
    }
    __syncthreads();
    return sh[0];
}

__inline__ __device__ float siluf(float v) { return v / (1.f + expf(-v)); }

// ---------------- rmsnorm -> split bf16 ----------------
__global__ void rmsnorm_split_kernel(const float* __restrict__ x, const float* __restrict__ w,
                                     __nv_bfloat16* __restrict__ oh, __nv_bfloat16* __restrict__ ol) {
    size_t row = blockIdx.x;
    const float* xr = x + row * DD;
    float ss = 0.f;
    for (int i = threadIdx.x; i < DD; i += blockDim.x) { float v = xr[i]; ss += v * v; }
    ss = blockReduceSum(ss);
    float inv = rsqrtf(ss / (float)DD + 1e-5f);
    for (int i = threadIdx.x; i < DD; i += blockDim.x) {
        float v = xr[i] * inv * w[i];
        __nv_bfloat16 h, l;
        split_bf16(v, h, l);
        oh[row * DD + i] = h;
        ol[row * DD + i] = l;
    }
}

// ---------------- transpose + split: out[n*K+k] = src[k*N+n], zero-pad to Npad ----------------
__global__ void transpose_split_kernel(const float* __restrict__ src, int K, int N,
                                       __nv_bfloat16* __restrict__ oh, __nv_bfloat16* __restrict__ ol,
                                       int Npad) {
    __shared__ float tile[32][33];
    int k0 = blockIdx.x * 32, n0 = blockIdx.y * 32;
#pragma unroll
    for (int i = 0; i < 4; i++) {
        int k = k0 + threadIdx.y + i * 8;
        int n = n0 + threadIdx.x;
        float v = (k < K && n < N) ? src[(size_t)k * N + n] : 0.f;
        tile[threadIdx.y + i * 8][threadIdx.x] = v;
    }
    __syncthreads();
#pragma unroll
    for (int i = 0; i < 4; i++) {
        int n = n0 + threadIdx.y + i * 8;
        int k = k0 + threadIdx.x;
        if (n < Npad && k < K) {
            float v = tile[threadIdx.x][threadIdx.y + i * 8];
            __nv_bfloat16 h, l;
            split_bf16(v, h, l);
            oh[(size_t)n * K + k] = h;
            ol[(size_t)n * K + k] = l;
        }
    }
}

// ---------------- elementwise split ----------------
__global__ void split_kernel(const float* __restrict__ src, __nv_bfloat16* __restrict__ oh,
                             __nv_bfloat16* __restrict__ ol, size_t n) {
    size_t i = (size_t)blockIdx.x * blockDim.x + threadIdx.x;
    if (i >= n) return;
    __nv_bfloat16 h, l;
    split_bf16(src[i], h, l);
    oh[i] = h;
    ol[i] = l;
}

// ---------------- mma.sync split-bf16 GEMM: C[M,N] = A[M,K] @ Bt[N,K]^T ----------------
// 128x128 CTA tile, 8 warps (64x32 each), k-chunk 32, 3-stage cp.async pipeline.
// 3-pass accumulation: Ah*Bh + Ah*Bl + Al*Bh in fp32.
#define TG_STAGE_BYTES 32768
#define TG_STAGES 3
#define TG_SMEM (TG_STAGES * TG_STAGE_BYTES)

__global__ __launch_bounds__(256, 1) void tgemm_kernel(const __nv_bfloat16* __restrict__ Ah,
                                                       const __nv_bfloat16* __restrict__ Al,
                                                       const __nv_bfloat16* __restrict__ Bh,
                                                       const __nv_bfloat16* __restrict__ Bl,
                                                       float* __restrict__ C, int M, int N, int K) {
    extern __shared__ char smg[];
    uint32_t sb = s2u(smg);
    const int tid = threadIdx.x;
    const int wid = tid >> 5, lid = tid & 31;
    const int m0 = blockIdx.y * 128, n0 = blockIdx.x * 128;
    const int wm = wid & 1, wn = wid >> 1;
    const int lr = lid & 15, lu = lid >> 4;
    const int NKC = K >> 5;

    // per-thread load mapping: 8 x 16B cp.async per 32-k chunk
    const __nv_bfloat16* gsrc[8];
    uint32_t dsto[8];
#pragma unroll
    for (int i = 0; i < 8; i++) {
        int q = tid + i * 256;
        int arr = q >> 9, idx = q & 511, row = idx >> 2, u = idx & 3;
        const __nv_bfloat16* base = (arr == 0) ? Ah : (arr == 1) ? Al : (arr == 2) ? Bh : Bl;
        int grow = ((arr < 2) ? m0 : n0) + row;
        gsrc[i] = base + (size_t)grow * K + u * 8;
        dsto[i] = (uint32_t)(arr * 8192 + row * 64 + ((u ^ (row & 3)) << 4));
    }

    auto issue = [&](int kc, int buf) {
        uint32_t sbuf = sb + buf * TG_STAGE_BYTES;
#pragma unroll
        for (int i = 0; i < 8; i++)
            asm volatile("cp.async.cg.shared.global [%0], [%1], 16;" ::
                         "r"(sbuf + dsto[i]), "l"((const void*)(gsrc[i] + (size_t)kc * 32))
                         : "memory");
    };

    float acc[4][4][4];
#pragma unroll
    for (int a = 0; a < 4; a++)
#pragma unroll
        for (int b = 0; b < 4; b++)
#pragma unroll
            for (int c = 0; c < 4; c++) acc[a][b][c] = 0.f;

    issue(0, 0);
    asm volatile("cp.async.commit_group;" ::: "memory");
    issue(1, 1);
    asm volatile("cp.async.commit_group;" ::: "memory");

    for (int kc = 0; kc < NKC; kc++) {
        asm volatile("cp.async.wait_group 1;" ::: "memory");
        __syncthreads();
        int nk = kc + 2;
        if (nk < NKC) issue(nk, nk % TG_STAGES);
        asm volatile("cp.async.commit_group;" ::: "memory");

        uint32_t ab = sb + (kc % TG_STAGES) * TG_STAGE_BYTES;
#pragma unroll
        for (int s = 0; s < 2; s++) {
            uint32_t ahf[4][4], alf[4][4], bhf[4][2], blf[4][2];
#pragma unroll
            for (int mt = 0; mt < 4; mt++) {
                int r = wm * 64 + mt * 16 + lr;
                int u = 2 * s + lu;
                uint32_t ad = ab + r * 64 + ((u ^ (r & 3)) << 4);
                LDSM4(ahf[mt][0], ahf[mt][1], ahf[mt][2], ahf[mt][3], ad);
                LDSM4(alf[mt][0], alf[mt][1], alf[mt][2], alf[mt][3], ad + 8192);
            }
#pragma unroll
            for (int p = 0; p < 2; p++) {
                int r = wn * 32 + p * 16 + lr;
                int u = 2 * s + lu;
                uint32_t bd = ab + 16384 + r * 64 + ((u ^ (r & 3)) << 4);
                uint32_t t0, t1, t2, t3;
                LDSM4(t0, t1, t2, t3, bd);
                bhf[p * 2 + 0][0] = t0; bhf[p * 2 + 0][1] = t2;
                bhf[p * 2 + 1][0] = t1; bhf[p * 2 + 1][1] = t3;
                LDSM4(t0, t1, t2, t3, bd + 8192);
                blf[p * 2 + 0][0] = t0; blf[p * 2 + 0][1] = t2;
                blf[p * 2 + 1][0] = t1; blf[p * 2 + 1][1] = t3;
            }
#pragma unroll
            for (int mt = 0; mt < 4; mt++)
#pragma unroll
                for (int nt = 0; nt < 4; nt++) {
                    MMA16816(acc[mt][nt], ahf[mt], bhf[nt]);
                    MMA16816(acc[mt][nt], ahf[mt], blf[nt]);
                    MMA16816(acc[mt][nt], alf[mt], bhf[nt]);
                }
        }
    }

    // epilogue: direct STG
#pragma unroll
    for (int mt = 0; mt < 4; mt++) {
        int r = m0 + wm * 64 + mt * 16 + (lid >> 2);
#pragma unroll
        for (int nt = 0; nt < 4; nt++) {
            int n = n0 + wn * 32 + nt * 8 + (lid & 3) * 2;
            if (n < N) {
                *(float2*)&C[(size_t)r * N + n] = make_float2(acc[mt][nt][0], acc[mt][nt][1]);
                *(float2*)&C[(size_t)(r + 8) * N + n] = make_float2(acc[mt][nt][2], acc[mt][nt][3]);
            }
        }
    }
}

// ---------------- conv + silu ----------------
__global__ void conv_kernel(const float* __restrict__ zx, const float* __restrict__ cw,
                            const float* __restrict__ cb, float* __restrict__ out) {
    size_t idx = (size_t)blockIdx.x * blockDim.x + threadIdx.x;
    if (idx >= (size_t)BB * LL * CONVDIM) return;
    int c = idx % CONVDIM;
    size_t rest = idx / CONVDIM;
    int t = rest % LL;
    int b = rest / LL;
    float acc = cb[c];
#pragma unroll
    for (int k = 0; k < 4; k++) {
        int tt = t - 3 + k;
        if (tt >= 0)
            acc += zx[((size_t)b * LL + tt) * DPROJ + DIN + c] * cw[k * CONVDIM + c];
    }
    out[idx] = siluf(acc);
}

// ---------------- dt softplus + dA ----------------
__global__ void dtda_kernel(const float* __restrict__ zx, const float* __restrict__ dtb,
                            const float* __restrict__ alog, float* __restrict__ dt,
                            float* __restrict__ dA) {
    size_t idx = (size_t)blockIdx.x * blockDim.x + threadIdx.x;
    if (idx >= (size_t)BB * LL * NH) return;
    int h = idx % NH;
    size_t row = idx / NH;
    float raw = zx[row * DPROJ + (DPROJ - NH) + h] + dtb[h];
    float sp = (raw > 20.f) ? raw : log1pf(expf(raw));
    dt[idx] = sp;
    dA[idx] = expf(sp * (-expf(alog[h])));
}

// ---------------- SSM scan ----------------
__global__ __launch_bounds__(1024, 1) void scan_kernel(const float* __restrict__ conv,
                                                       const float* __restrict__ dt,
                                                       const float* __restrict__ dA,
                                                       const float* __restrict__ Dp,
                                                       float* __restrict__ y) {
    int b = blockIdx.x >> 5;
    int h = blockIdx.x & 31;
    int tid = threadIdx.x;
    int p = tid >> 4;
    int ln = tid & 15;
    __shared__ float sB[2][128], sC[2][128], sx[2][64];
    __shared__ float sdt[2], sdA[2];
    float S[8];
#pragma unroll
    for (int j = 0; j < 8; j++) S[j] = 0.f;
    float Dh = Dp[h];

    {
        const float* row = conv + ((size_t)b * LL) * CONVDIM;
        if (tid < 128) sB[0][tid] = row[2048 + tid];
        else if (tid < 256) sC[0][tid - 128] = row[2176 + (tid - 128)];
        else if (tid < 320) sx[0][tid - 256] = row[h * HD + (tid - 256)];
        else if (tid == 320) {
            size_t o = ((size_t)b * LL) * NH + h;
            sdt[0] = dt[o]; sdA[0] = dA[o];
        }
    }
    for (int t = 0; t < LL; t++) {
        int cur = t & 1;
        __syncthreads();
        if (t + 1 < LL) {
            int nb = cur ^ 1;
            const float* row = conv + ((size_t)b * LL + t + 1) * CONVDIM;
            if (tid < 128) sB[nb][tid] = row[2048 + tid];
            else if (tid < 256) sC[nb][tid - 128] = row[2176 + (tid - 128)];
            else if (tid < 320) sx[nb][tid - 256] = row[h * HD + (tid - 256)];
            else if (tid == 320) {
                size_t o = ((size_t)b * LL + t + 1) * NH + h;
                sdt[nb] = dt[o]; sdA[nb] = dA[o];
            }
        }
        float xv = sx[cur][p];
        float dtx = sdt[cur] * xv;
        float a = sdA[cur];
        float part = 0.f;
#pragma unroll
        for (int j = 0; j < 8; j++) {
            int n = ln + 16 * j;
            S[j] = S[j] * a + dtx * sB[cur][n];
            part += S[j] * sC[cur][n];
        }
        part += __shfl_down_sync(0xffffffffu, part, 8, 16);
        part += __shfl_down_sync(0xffffffffu, part, 4, 16);
        part += __shfl_down_sync(0xffffffffu, part, 2, 16);
        part += __shfl_down_sync(0xffffffffu, part, 1, 16);
        if (ln == 0) y[((size_t)b * LL + t) * DIN + h * HD + p] = part + Dh * xv;
    }
}

// ---------------- gated rmsnorm -> split bf16 ----------------
__global__ void gnorm_split_kernel(const float* __restrict__ y, const float* __restrict__ zx,
                                   const float* __restrict__ gw, __nv_bfloat16* __restrict__ oh,
                                   __nv_bfloat16* __restrict__ ol) {
    size_t row = blockIdx.x;
    const float* yr = y + row * DIN;
    const float* zr = zx + row * DPROJ;
    float v[8];
    float ss = 0.f;
#pragma unroll
    for (int u = 0; u < 8; u++) {
        int i = threadIdx.x + u * 256;
        float z = zr[i];
        float val = yr[i] * siluf(z);
        v[u] = val;
        ss += val * val;
    }
    ss = blockReduceSum(ss);
    float inv = rsqrtf(ss / (float)DIN + 1e-5f);
#pragma unroll
    for (int u = 0; u < 8; u++) {
        int i = threadIdx.x + u * 256;
        float val = v[u] * inv * gw[i];
        __nv_bfloat16 h, l;
        split_bf16(val, h, l);
        oh[row * DIN + i] = h;
        ol[row * DIN + i] = l;
    }
}

// ---------------- cumsum passes ----------------
__global__ void chunk_sum_kernel(const float* __restrict__ Q, float* __restrict__ cs) {
    int c = (blockIdx.x & 3) * 256 + threadIdx.x;
    int chunk = (blockIdx.x >> 2) & (NCHUNK - 1);
    int b = blockIdx.x >> 5;
    float s = 0.f;
    size_t base = ((size_t)b * LL + (size_t)chunk * CHL) * DD + c;
    for (int l = 0; l < CHL; l++) s += Q[base + (size_t)l * DD];
    cs[((size_t)b * NCHUNK + chunk) * DD + c] = s;
}

__global__ void scan_chunks_kernel(float* __restrict__ cs) {
    int i = blockIdx.x * blockDim.x + threadIdx.x;
    if (i >= BB * DD) return;
    int b = i / DD, c = i % DD;
    float acc = 0.f;
#pragma unroll
    for (int ch = 0; ch < NCHUNK; ch++) {
        size_t o = ((size_t)b * NCHUNK + ch) * DD + c;
        float v = cs[o];
        cs[o] = acc;
        acc += v;
    }
}

__global__ void final_kernel(const float* __restrict__ x, const float* __restrict__ P,
                             const float* __restrict__ R, const float* __restrict__ Q,
                             const float* __restrict__ cs, float* __restrict__ out) {
    int c = (blockIdx.x & 3) * 256 + threadIdx.x;
    int chunk = (blockIdx.x >> 2) & (NCHUNK - 1);
    int b = blockIdx.x >> 5;
    float acc = cs[((size_t)b * NCHUNK + chunk) * DD + c];
    size_t base = ((size_t)b * LL + (size_t)chunk * CHL) * DD + c;
    for (int l = 0; l < CHL; l++) {
        size_t idx = base + (size_t)l * DD;
        acc += Q[idx];
        out[idx] = x[idx] + P[idx] + R[idx] + acc;
    }
}

// ---------------- launch ----------------
extern "C" void kernel_launch(void* const* d_in, const int* in_sizes, int n_in,
                              void* d_out, int out_size) {
    const float* x       = (const float*)d_in[0];
    const float* norm_w  = (const float*)d_in[1];
    const float* in_proj = (const float*)d_in[2];
    const float* conv_W  = (const float*)d_in[3];
    const float* conv_b  = (const float*)d_in[4];
    const float* dt_bias = (const float*)d_in[5];
    const float* A_log   = (const float*)d_in[6];
    const float* Dvec    = (const float*)d_in[7];
    const float* gnorm_w = (const float*)d_in[8];
    const float* zero_W  = (const float*)d_in[9];
    const float* one_W   = (const float*)d_in[10];
    const float* fusion  = (const float*)d_in[11];
    float* out = (float*)d_out;

    float *zx, *conv, *dt, *dA, *y, *P, *Q, *R, *Wz, *Wc, *cs;
    __nv_bfloat16 *xnh, *xnl, *Wpth, *Wptl, *Fzth, *Fztl, *Foth, *Fotl, *Fmth, *Fmtl;
    __nv_bfloat16 *zwh, *zwl, *owh, *owl, *Wzth, *Wztl, *Wcth, *Wctl, *yh, *yl;
    cudaGetSymbolAddress((void**)&zx, g_zx);
    cudaGetSymbolAddress((void**)&conv, g_conv);
    cudaGetSymbolAddress((void**)&dt, g_dt);
    cudaGetSymbolAddress((void**)&dA, g_dA);
    cudaGetSymbolAddress((void**)&y, g_y);
    cudaGetSymbolAddress((void**)&P, g_P);
    cudaGetSymbolAddress((void**)&Q, g_Q);
    cudaGetSymbolAddress((void**)&R, g_R);
    cudaGetSymbolAddress((void**)&Wz, g_Wz);
    cudaGetSymbolAddress((void**)&Wc, g_Wc);
    cudaGetSymbolAddress((void**)&cs, g_cs);
    cudaGetSymbolAddress((void**)&xnh, g_xnh);
    cudaGetSymbolAddress((void**)&xnl, g_xnl);
    cudaGetSymbolAddress((void**)&Wpth, g_Wpth);
    cudaGetSymbolAddress((void**)&Wptl, g_Wptl);
    cudaGetSymbolAddress((void**)&Fzth, g_Fzth);
    cudaGetSymbolAddress((void**)&Fztl, g_Fztl);
    cudaGetSymbolAddress((void**)&Foth, g_Foth);
    cudaGetSymbolAddress((void**)&Fotl, g_Fotl);
    cudaGetSymbolAddress((void**)&Fmth, g_Fmth);
    cudaGetSymbolAddress((void**)&Fmtl, g_Fmtl);
    cudaGetSymbolAddress((void**)&zwh, g_zwh);
    cudaGetSymbolAddress((void**)&zwl, g_zwl);
    cudaGetSymbolAddress((void**)&owh, g_owh);
    cudaGetSymbolAddress((void**)&owl, g_owl);
    cudaGetSymbolAddress((void**)&Wzth, g_Wzth);
    cudaGetSymbolAddress((void**)&Wztl, g_Wztl);
    cudaGetSymbolAddress((void**)&Wcth, g_Wcth);
    cudaGetSymbolAddress((void**)&Wctl, g_Wctl);
    cudaGetSymbolAddress((void**)&yh, g_yh);
    cudaGetSymbolAddress((void**)&yl, g_yl);

    const int M = BB * LL;
    cudaFuncSetAttribute(tgemm_kernel, cudaFuncAttributeMaxDynamicSharedMemorySize, TG_SMEM);

    dim3 tb(32, 8);

    // 1. xn = rmsnorm(x) -> hi/lo bf16
    rmsnorm_split_kernel<<<M, 256>>>(x, norm_w, xnh, xnl);

    // 2. transpose-split in_proj_W [1024,4384] -> [4480,1024]
    transpose_split_kernel<<<dim3(DD / 32, NPADPROJ / 32), tb>>>(in_proj, DD, DPROJ, Wpth, Wptl, NPADPROJ);

    // 3. zx = xn @ in_proj_W
    tgemm_kernel<<<dim3(NPADPROJ / 128, M / 128), 256, TG_SMEM>>>(xnh, xnl, Wpth, Wptl, zx, M, DPROJ, DD);

    // 4. conv + silu ; dt/dA
    {
        size_t tot = (size_t)BB * LL * CONVDIM;
        conv_kernel<<<(unsigned)((tot + 255) / 256), 256>>>(zx, conv_W, conv_b, conv);
        size_t tot2 = (size_t)BB * LL * NH;
        dtda_kernel<<<(unsigned)((tot2 + 255) / 256), 256>>>(zx, dt_bias, A_log, dt, dA);
    }

    // 5. SSM scan
    scan_kernel<<<BB * NH, 1024>>>(conv, dt, dA, Dvec, y);

    // 6. side-path prep: split zero_W/one_W, transpose fusion blocks
    {
        size_t n = (size_t)DD * DIN;
        split_kernel<<<(unsigned)((n + 255) / 256), 256>>>(zero_W, zwh, zwl, n);
        split_kernel<<<(unsigned)((n + 255) / 256), 256>>>(one_W, owh, owl, n);
        transpose_split_kernel<<<dim3(DIN / 32, DD / 32), tb>>>(fusion, DIN, DD, Fmth, Fmtl, DD);
        transpose_split_kernel<<<dim3(DIN / 32, DD / 32), tb>>>(fusion + (size_t)DIN * DD, DIN, DD, Fzth, Fztl, DD);
        transpose_split_kernel<<<dim3(DIN / 32, DD / 32), tb>>>(fusion + (size_t)2 * DIN * DD, DIN, DD, Foth, Fotl, DD);
    }

    // 7. combines: Wz = zero_W @ Fz ; Wc = one_W @ Fo ; then transpose-split
    tgemm_kernel<<<dim3(8, 8), 256, TG_SMEM>>>(zwh, zwl, Fzth, Fztl, Wz, DD, DD, DIN);
    tgemm_kernel<<<dim3(8, 8), 256, TG_SMEM>>>(owh, owl, Foth, Fotl, Wc, DD, DD, DIN);
    transpose_split_kernel<<<dim3(DD / 32, DD / 32), tb>>>(Wz, DD, DD, Wzth, Wztl, DD);
    transpose_split_kernel<<<dim3(DD / 32, DD / 32), tb>>>(Wc, DD, DD, Wcth, Wctl, DD);

    // 8. P = xn @ Wz ; Q = xn @ Wc
    tgemm_kernel<<<dim3(8, M / 128), 256, TG_SMEM>>>(xnh, xnl, Wzth, Wztl, P, M, DD, DD);
    tgemm_kernel<<<dim3(8, M / 128), 256, TG_SMEM>>>(xnh, xnl, Wcth, Wctl, Q, M, DD, DD);

    // 9. gated rmsnorm -> y hi/lo
    gnorm_split_kernel<<<M, 256>>>(y, zx, gnorm_w, yh, yl);

    // 10. R = y @ Fm
    tgemm_kernel<<<dim3(8, M / 128), 256, TG_SMEM>>>(yh, yl, Fmth, Fmtl, R, M, DD, DIN);

    // 11. cumsum + final
    chunk_sum_kernel<<<BB * NCHUNK * 4, 256>>>(Q, cs);
    scan_chunks_kernel<<<(BB * DD + 255) / 256, 256>>>(cs);
    final_kernel<<<BB * NCHUNK * 4, 256>>>(x, P, R, Q, cs, out);
}

// round 9
// speedup vs baseline: 2.3023x; 1.5581x over previous
#include <cuda_runtime.h>
#include <cuda_bf16.h>
#include <math.h>
#include <stdint.h>

#define BB 2
#define LL 4096
#define DD 1024
#define DIN 2048
#define DSTATE 128
#define NH 32
#define HD 64
#define CONVDIM 2304
#define DPROJ 4384
#define NPADPROJ 4480
#define NCHUNK 8
#define CHL (LL / NCHUNK)

// ---------------- scratch (device globals) ----------------
__device__ float g_zx[BB * LL * DPROJ];
__device__ float g_conv[BB * LL * CONVDIM];
__device__ float g_dt[BB * LL * NH];
__device__ float g_dA[BB * LL * NH];
__device__ float g_y1[BB * LL * DIN];   // scan partial, n in [0,64)
__device__ float g_y2[BB * LL * DIN];   // scan partial, n in [64,128)
__device__ float g_P[BB * LL * DD];
__device__ float g_Q[BB * LL * DD];
__device__ float g_R[BB * LL * DD];
__device__ float g_Wz[DD * DD];
__device__ float g_Wc[DD * DD];
__device__ float g_cs[BB * NCHUNK * DD];

__device__ __nv_bfloat16 g_xnh[BB * LL * DD], g_xnl[BB * LL * DD];
__device__ __nv_bfloat16 g_Wpth[NPADPROJ * DD], g_Wptl[NPADPROJ * DD];
__device__ __nv_bfloat16 g_Fzth[DD * DIN], g_Fztl[DD * DIN];
__device__ __nv_bfloat16 g_Foth[DD * DIN], g_Fotl[DD * DIN];
__device__ __nv_bfloat16 g_Fmth[DD * DIN], g_Fmtl[DD * DIN];
__device__ __nv_bfloat16 g_zwh[DD * DIN], g_zwl[DD * DIN];
__device__ __nv_bfloat16 g_owh[DD * DIN], g_owl[DD * DIN];
__device__ __nv_bfloat16 g_Wzth[DD * DD], g_Wztl[DD * DD];
__device__ __nv_bfloat16 g_Wcth[DD * DD], g_Wctl[DD * DD];
__device__ __nv_bfloat16 g_yh[BB * LL * DIN], g_yl[BB * LL * DIN];

// ---------------- helpers ----------------
__device__ __forceinline__ uint32_t s2u(const void* p) {
    uint32_t a;
    asm("{ .reg .u64 t; cvta.to.shared.u64 t, %1; cvt.u32.u64 %0, t; }" : "=r"(a) : "l"(p));
    return a;
}

#define LDSM4(r0, r1, r2, r3, addr)                                                         \
    asm volatile("ldmatrix.sync.aligned.m8n8.x4.shared.b16 {%0,%1,%2,%3}, [%4];"            \
                 : "=r"(r0), "=r"(r1), "=r"(r2), "=r"(r3) : "r"(addr))

#define MMA16816(c, a, b)                                                                   \
    asm volatile("mma.sync.aligned.m16n8k16.row.col.f32.bf16.bf16.f32 "                     \
                 "{%0,%1,%2,%3}, {%4,%5,%6,%7}, {%8,%9}, {%0,%1,%2,%3};"                    \
                 : "+f"((c)[0]), "+f"((c)[1]), "+f"((c)[2]), "+f"((c)[3])                   \
                 : "r"((a)[0]), "r"((a)[1]), "r"((a)[2]), "r"((a)[3]),                      \
                   "r"((b)[0]), "r"((b)[1]))

__device__ __forceinline__ void split_bf16(float v, __nv_bfloat16& h, __nv_bfloat16& l) {
    h = __float2bfloat16(v);
    l = __float2bfloat16(v - __bfloat162float(h));
}

__inline__ __device__ float blockReduceSum(float v) {
    __shared__ float sh[32];
    int lane = threadIdx.x & 31, wid = threadIdx.x >> 5;
#pragma unroll
    for (int o = 16; o > 0; o >>= 1) v += __shfl_down_sync(0xffffffffu, v, o);
    if (lane == 0) sh[wid] = v;
    __syncthreads();
    v = (threadIdx.x < (blockDim.x >> 5)) ? sh[lane] : 0.f;
    if (wid == 0) {
#pragma unroll
        for (int o = 16; o > 0; o >>= 1) v += __shfl_down_sync(0xffffffffu, v, o);
        if (lane == 0) sh[0] = v;
    }
    __syncthreads();
    return sh[0];
}

__inline__ __device__ float siluf(float v) { return v / (1.f + expf(-v)); }

// ---------------- rmsnorm -> split bf16 ----------------
__global__ void rmsnorm_split_kernel(const float* __restrict__ x, const float* __restrict__ w,
                                     __nv_bfloat16* __restrict__ oh, __nv_bfloat16* __restrict__ ol) {
    size_t row = blockIdx.x;
    const float* xr = x + row * DD;
    float ss = 0.f;
    for (int i = threadIdx.x; i < DD; i += blockDim.x) { float v = xr[i]; ss += v * v; }
    ss = blockReduceSum(ss);
    float inv = rsqrtf(ss / (float)DD + 1e-5f);
    for (int i = threadIdx.x; i < DD; i += blockDim.x) {
        float v = xr[i] * inv * w[i];
        __nv_bfloat16 h, l;
        split_bf16(v, h, l);
        oh[row * DD + i] = h;
        ol[row * DD + i] = l;
    }
}

// ---------------- transpose + split ----------------
__global__ void transpose_split_kernel(const float* __restrict__ src, int K, int N,
                                       __nv_bfloat16* __restrict__ oh, __nv_bfloat16* __restrict__ ol,
                                       int Npad) {
    __shared__ float tile[32][33];
    int k0 = blockIdx.x * 32, n0 = blockIdx.y * 32;
#pragma unroll
    for (int i = 0; i < 4; i++) {
        int k = k0 + threadIdx.y + i * 8;
        int n = n0 + threadIdx.x;
        float v = (k < K && n < N) ? src[(size_t)k * N + n] : 0.f;
        tile[threadIdx.y + i * 8][threadIdx.x] = v;
    }
    __syncthreads();
#pragma unroll
    for (int i = 0; i < 4; i++) {
        int n = n0 + threadIdx.y + i * 8;
        int k = k0 + threadIdx.x;
        if (n < Npad && k < K) {
            float v = tile[threadIdx.x][threadIdx.y + i * 8];
            __nv_bfloat16 h, l;
            split_bf16(v, h, l);
            oh[(size_t)n * K + k] = h;
            ol[(size_t)n * K + k] = l;
        }
    }
}

// ---------------- elementwise split ----------------
__global__ void split_kernel(const float* __restrict__ src, __nv_bfloat16* __restrict__ oh,
                             __nv_bfloat16* __restrict__ ol, size_t n) {
    size_t i = (size_t)blockIdx.x * blockDim.x + threadIdx.x;
    if (i >= n) return;
    __nv_bfloat16 h, l;
    split_bf16(src[i], h, l);
    oh[i] = h;
    ol[i] = l;
}

// ---------------- mma.sync split-bf16 GEMM (unchanged, R4-passing) ----------------
#define TG_STAGE_BYTES 32768
#define TG_STAGES 3
#define TG_SMEM (TG_STAGES * TG_STAGE_BYTES)

__global__ __launch_bounds__(256, 1) void tgemm_kernel(const __nv_bfloat16* __restrict__ Ah,
                                                       const __nv_bfloat16* __restrict__ Al,
                                                       const __nv_bfloat16* __restrict__ Bh,
                                                       const __nv_bfloat16* __restrict__ Bl,
                                                       float* __restrict__ C, int M, int N, int K) {
    extern __shared__ char smg[];
    uint32_t sb = s2u(smg);
    const int tid = threadIdx.x;
    const int wid = tid >> 5, lid = tid & 31;
    const int m0 = blockIdx.y * 128, n0 = blockIdx.x * 128;
    const int wm = wid & 1, wn = wid >> 1;
    const int lr = lid & 15, lu = lid >> 4;
    const int NKC = K >> 5;

    const __nv_bfloat16* gsrc[8];
    uint32_t dsto[8];
#pragma unroll
    for (int i = 0; i < 8; i++) {
        int q = tid + i * 256;
        int arr = q >> 9, idx = q & 511, row = idx >> 2, u = idx & 3;
        const __nv_bfloat16* base = (arr == 0) ? Ah : (arr == 1) ? Al : (arr == 2) ? Bh : Bl;
        int grow = ((arr < 2) ? m0 : n0) + row;
        gsrc[i] = base + (size_t)grow * K + u * 8;
        dsto[i] = (uint32_t)(arr * 8192 + row * 64 + ((u ^ (row & 3)) << 4));
    }

    auto issue = [&](int kc, int buf) {
        uint32_t sbuf = sb + buf * TG_STAGE_BYTES;
#pragma unroll
        for (int i = 0; i < 8; i++)
            asm volatile("cp.async.cg.shared.global [%0], [%1], 16;" ::
                         "r"(sbuf + dsto[i]), "l"((const void*)(gsrc[i] + (size_t)kc * 32))
                         : "memory");
    };

    float acc[4][4][4];
#pragma unroll
    for (int a = 0; a < 4; a++)
#pragma unroll
        for (int b = 0; b < 4; b++)
#pragma unroll
            for (int c = 0; c < 4; c++) acc[a][b][c] = 0.f;

    issue(0, 0);
    asm volatile("cp.async.commit_group;" ::: "memory");
    issue(1, 1);
    asm volatile("cp.async.commit_group;" ::: "memory");

    for (int kc = 0; kc < NKC; kc++) {
        asm volatile("cp.async.wait_group 1;" ::: "memory");
        __syncthreads();
        int nk = kc + 2;
        if (nk < NKC) issue(nk, nk % TG_STAGES);
        asm volatile("cp.async.commit_group;" ::: "memory");

        uint32_t ab = sb + (kc % TG_STAGES) * TG_STAGE_BYTES;
#pragma unroll
        for (int s = 0; s < 2; s++) {
            uint32_t ahf[4][4], alf[4][4], bhf[4][2], blf[4][2];
#pragma unroll
            for (int mt = 0; mt < 4; mt++) {
                int r = wm * 64 + mt * 16 + lr;
                int u = 2 * s + lu;
                uint32_t ad = ab + r * 64 + ((u ^ (r & 3)) << 4);
                LDSM4(ahf[mt][0], ahf[mt][1], ahf[mt][2], ahf[mt][3], ad);
                LDSM4(alf[mt][0], alf[mt][1], alf[mt][2], alf[mt][3], ad + 8192);
            }
#pragma unroll
            for (int p = 0; p < 2; p++) {
                int r = wn * 32 + p * 16 + lr;
                int u = 2 * s + lu;
                uint32_t bd = ab + 16384 + r * 64 + ((u ^ (r & 3)) << 4);
                uint32_t t0, t1, t2, t3;
                LDSM4(t0, t1, t2, t3, bd);
                bhf[p * 2 + 0][0] = t0; bhf[p * 2 + 0][1] = t2;
                bhf[p * 2 + 1][0] = t1; bhf[p * 2 + 1][1] = t3;
                LDSM4(t0, t1, t2, t3, bd + 8192);
                blf[p * 2 + 0][0] = t0; blf[p * 2 + 0][1] = t2;
                blf[p * 2 + 1][0] = t1; blf[p * 2 + 1][1] = t3;
            }
#pragma unroll
            for (int mt = 0; mt < 4; mt++)
#pragma unroll
                for (int nt = 0; nt < 4; nt++) {
                    MMA16816(acc[mt][nt], ahf[mt], bhf[nt]);
                    MMA16816(acc[mt][nt], ahf[mt], blf[nt]);
                    MMA16816(acc[mt][nt], alf[mt], bhf[nt]);
                }
        }
    }

#pragma unroll
    for (int mt = 0; mt < 4; mt++) {
        int r = m0 + wm * 64 + mt * 16 + (lid >> 2);
#pragma unroll
        for (int nt = 0; nt < 4; nt++) {
            int n = n0 + wn * 32 + nt * 8 + (lid & 3) * 2;
            if (n < N) {
                *(float2*)&C[(size_t)r * N + n] = make_float2(acc[mt][nt][0], acc[mt][nt][1]);
                *(float2*)&C[(size_t)(r + 8) * N + n] = make_float2(acc[mt][nt][2], acc[mt][nt][3]);
            }
        }
    }
}

// ---------------- conv + silu ----------------
__global__ void conv_kernel(const float* __restrict__ zx, const float* __restrict__ cw,
                            const float* __restrict__ cb, float* __restrict__ out) {
    size_t idx = (size_t)blockIdx.x * blockDim.x + threadIdx.x;
    if (idx >= (size_t)BB * LL * CONVDIM) return;
    int c = idx % CONVDIM;
    size_t rest = idx / CONVDIM;
    int t = rest % LL;
    int b = rest / LL;
    float acc = cb[c];
#pragma unroll
    for (int k = 0; k < 4; k++) {
        int tt = t - 3 + k;
        if (tt >= 0)
            acc += zx[((size_t)b * LL + tt) * DPROJ + DIN + c] * cw[k * CONVDIM + c];
    }
    out[idx] = siluf(acc);
}

// ---------------- dt softplus + dA ----------------
__global__ void dtda_kernel(const float* __restrict__ zx, const float* __restrict__ dtb,
                            const float* __restrict__ alog, float* __restrict__ dtO,
                            float* __restrict__ dAO) {
    size_t idx = (size_t)blockIdx.x * blockDim.x + threadIdx.x;
    if (idx >= (size_t)BB * LL * NH) return;
    int h = idx % NH;
    size_t row = idx / NH;
    float raw = zx[row * DPROJ + (DPROJ - NH) + h] + dtb[h];
    float sp = (raw > 20.f) ? raw : log1pf(expf(raw));
    dtO[idx] = sp;
    dAO[idx] = expf(sp * (-expf(alog[h])));
}

// ---------------- SSM scan: chunked cp.async pipeline, 128 blocks, 512 threads ----------------
#define SC_T 16
#define SC_NCH (LL / SC_T)

__global__ __launch_bounds__(512, 1) void scan_kernel(const float* __restrict__ conv,
                                                      const float* __restrict__ dtp,
                                                      const float* __restrict__ dAp,
                                                      float* __restrict__ yp0,
                                                      float* __restrict__ yp1) {
    const int s = blockIdx.x & 1;
    const int h = (blockIdx.x >> 1) & 31;
    const int b = blockIdx.x >> 6;
    float* __restrict__ yp = s ? yp1 : yp0;
    const int n0 = s * 64;
    const int tid = threadIdx.x;
    const int p = tid >> 3, ln = tid & 7;

    __shared__ __align__(16) float sB[3][SC_T][64];
    __shared__ __align__(16) float sC[3][SC_T][64];
    __shared__ __align__(16) float sx[3][SC_T][64];
    __shared__ float sdt[3][SC_T], sdA[3][SC_T];

    auto load = [&](int c, int st) {
#pragma unroll
        for (int q = tid; q < 800; q += 512) {
            if (q < 768) {
                int t = q / 48, k = q % 48;
                int arr = k >> 4, o = (k & 15) * 4;
                size_t g = (size_t)b * LL + (size_t)c * SC_T + t;
                const float* src;
                uint32_t d;
                if (arr == 0) { src = conv + g * CONVDIM + 2048 + n0 + o; d = s2u(&sB[st][t][o]); }
                else if (arr == 1) { src = conv + g * CONVDIM + 2176 + n0 + o; d = s2u(&sC[st][t][o]); }
                else { src = conv + g * CONVDIM + h * HD + o; d = s2u(&sx[st][t][o]); }
                asm volatile("cp.async.cg.shared.global [%0], [%1], 16;" :: "r"(d), "l"((const void*)src) : "memory");
            } else if (q < 784) {
                int t = q - 768;
                size_t g = (size_t)b * LL + (size_t)c * SC_T + t;
                uint32_t d = s2u(&sdt[st][t]);
                asm volatile("cp.async.ca.shared.global [%0], [%1], 4;" :: "r"(d), "l"((const void*)(dtp + g * NH + h)) : "memory");
            } else {
                int t = q - 784;
                size_t g = (size_t)b * LL + (size_t)c * SC_T + t;
                uint32_t d = s2u(&sdA[st][t]);
                asm volatile("cp.async.ca.shared.global [%0], [%1], 4;" :: "r"(d), "l"((const void*)(dAp + g * NH + h)) : "memory");
            }
        }
    };

    float S[8];
#pragma unroll
    for (int j = 0; j < 8; j++) S[j] = 0.f;

    load(0, 0);
    asm volatile("cp.async.commit_group;" ::: "memory");
    load(1, 1);
    asm volatile("cp.async.commit_group;" ::: "memory");

    for (int c = 0; c < SC_NCH; c++) {
        asm volatile("cp.async.wait_group 1;" ::: "memory");
        __syncthreads();
        if (c + 2 < SC_NCH) load(c + 2, (c + 2) % 3);
        asm volatile("cp.async.commit_group;" ::: "memory");

        const int st = c % 3;
        size_t gbase = ((size_t)b * LL + (size_t)c * SC_T) * DIN + h * HD + p;
#pragma unroll
        for (int t = 0; t < SC_T; t++) {
            float a = sdA[st][t];
            float dv = sdt[st][t];
            float xv = sx[st][t][p];
            float dtx = dv * xv;
            float4 b0 = *(float4*)&sB[st][t][ln * 8];
            float4 b1 = *(float4*)&sB[st][t][ln * 8 + 4];
            float4 c0 = *(float4*)&sC[st][t][ln * 8];
            float4 c1 = *(float4*)&sC[st][t][ln * 8 + 4];
            S[0] = fmaf(S[0], a, dtx * b0.x);
            S[1] = fmaf(S[1], a, dtx * b0.y);
            S[2] = fmaf(S[2], a, dtx * b0.z);
            S[3] = fmaf(S[3], a, dtx * b0.w);
            S[4] = fmaf(S[4], a, dtx * b1.x);
            S[5] = fmaf(S[5], a, dtx * b1.y);
            S[6] = fmaf(S[6], a, dtx * b1.z);
            S[7] = fmaf(S[7], a, dtx * b1.w);
            float part = S[0] * c0.x;
            part = fmaf(S[1], c0.y, part);
            part = fmaf(S[2], c0.z, part);
            part = fmaf(S[3], c0.w, part);
            part = fmaf(S[4], c1.x, part);
            part = fmaf(S[5], c1.y, part);
            part = fmaf(S[6], c1.z, part);
            part = fmaf(S[7], c1.w, part);
            part += __shfl_down_sync(0xffffffffu, part, 4, 8);
            part += __shfl_down_sync(0xffffffffu, part, 2, 8);
            part += __shfl_down_sync(0xffffffffu, part, 1, 8);
            if (ln == 0) yp[gbase + (size_t)t * DIN] = part;
        }
    }
}

// ---------------- gated rmsnorm (merges scan partials + D*x) -> split bf16 ----------------
__global__ void gnorm_split_kernel(const float* __restrict__ y1, const float* __restrict__ y2,
                                   const float* __restrict__ conv, const float* __restrict__ Dp,
                                   const float* __restrict__ zx, const float* __restrict__ gw,
                                   __nv_bfloat16* __restrict__ oh, __nv_bfloat16* __restrict__ ol) {
    size_t row = blockIdx.x;
    const float* zr = zx + row * DPROJ;
    float v[8];
    float ss = 0.f;
#pragma unroll
    for (int u = 0; u < 8; u++) {
        int i = threadIdx.x + u * 256;
        float xv = conv[row * CONVDIM + i];
        float yv = y1[row * DIN + i] + y2[row * DIN + i] + Dp[i >> 6] * xv;
        float z = zr[i];
        float val = yv * siluf(z);
        v[u] = val;
        ss += val * val;
    }
    ss = blockReduceSum(ss);
    float inv = rsqrtf(ss / (float)DIN + 1e-5f);
#pragma unroll
    for (int u = 0; u < 8; u++) {
        int i = threadIdx.x + u * 256;
        float val = v[u] * inv * gw[i];
        __nv_bfloat16 h, l;
        split_bf16(val, h, l);
        oh[row * DIN + i] = h;
        ol[row * DIN + i] = l;
    }
}

// ---------------- cumsum passes ----------------
__global__ void chunk_sum_kernel(const float* __restrict__ Q, float* __restrict__ cs) {
    int c = (blockIdx.x & 3) * 256 + threadIdx.x;
    int chunk = (blockIdx.x >> 2) & (NCHUNK - 1);
    int b = blockIdx.x >> 5;
    float s = 0.f;
    size_t base = ((size_t)b * LL + (size_t)chunk * CHL) * DD + c;
    for (int l = 0; l < CHL; l++) s += Q[base + (size_t)l * DD];
    cs[((size_t)b * NCHUNK + chunk) * DD + c] = s;
}

__global__ void scan_chunks_kernel(float* __restrict__ cs) {
    int i = blockIdx.x * blockDim.x + threadIdx.x;
    if (i >= BB * DD) return;
    int b = i / DD, c = i % DD;
    float acc = 0.f;
#pragma unroll
    for (int ch = 0; ch < NCHUNK; ch++) {
        size_t o = ((size_t)b * NCHUNK + ch) * DD + c;
        float v = cs[o];
        cs[o] = acc;
        acc += v;
    }
}

__global__ void final_kernel(const float* __restrict__ x, const float* __restrict__ P,
                             const float* __restrict__ R, const float* __restrict__ Q,
                             const float* __restrict__ cs, float* __restrict__ out) {
    int c = (blockIdx.x & 3) * 256 + threadIdx.x;
    int chunk = (blockIdx.x >> 2) & (NCHUNK - 1);
    int b = blockIdx.x >> 5;
    float acc = cs[((size_t)b * NCHUNK + chunk) * DD + c];
    size_t base = ((size_t)b * LL + (size_t)chunk * CHL) * DD + c;
    for (int l = 0; l < CHL; l++) {
        size_t idx = base + (size_t)l * DD;
        acc += Q[idx];
        out[idx] = x[idx] + P[idx] + R[idx] + acc;
    }
}

// ---------------- launch ----------------
extern "C" void kernel_launch(void* const* d_in, const int* in_sizes, int n_in,
                              void* d_out, int out_size) {
    const float* x       = (const float*)d_in[0];
    const float* norm_w  = (const float*)d_in[1];
    const float* in_proj = (const float*)d_in[2];
    const float* conv_W  = (const float*)d_in[3];
    const float* conv_b  = (const float*)d_in[4];
    const float* dt_bias = (const float*)d_in[5];
    const float* A_log   = (const float*)d_in[6];
    const float* Dvec    = (const float*)d_in[7];
    const float* gnorm_w = (const float*)d_in[8];
    const float* zero_W  = (const float*)d_in[9];
    const float* one_W   = (const float*)d_in[10];
    const float* fusion  = (const float*)d_in[11];
    float* out = (float*)d_out;

    float *zx, *conv, *dt, *dA, *y1, *y2, *P, *Q, *R, *Wz, *Wc, *cs;
    __nv_bfloat16 *xnh, *xnl, *Wpth, *Wptl, *Fzth, *Fztl, *Foth, *Fotl, *Fmth, *Fmtl;
    __nv_bfloat16 *zwh, *zwl, *owh, *owl, *Wzth, *Wztl, *Wcth, *Wctl, *yh, *yl;
    cudaGetSymbolAddress((void**)&zx, g_zx);
    cudaGetSymbolAddress((void**)&conv, g_conv);
    cudaGetSymbolAddress((void**)&dt, g_dt);
    cudaGetSymbolAddress((void**)&dA, g_dA);
    cudaGetSymbolAddress((void**)&y1, g_y1);
    cudaGetSymbolAddress((void**)&y2, g_y2);
    cudaGetSymbolAddress((void**)&P, g_P);
    cudaGetSymbolAddress((void**)&Q, g_Q);
    cudaGetSymbolAddress((void**)&R, g_R);
    cudaGetSymbolAddress((void**)&Wz, g_Wz);
    cudaGetSymbolAddress((void**)&Wc, g_Wc);
    cudaGetSymbolAddress((void**)&cs, g_cs);
    cudaGetSymbolAddress((void**)&xnh, g_xnh);
    cudaGetSymbolAddress((void**)&xnl, g_xnl);
    cudaGetSymbolAddress((void**)&Wpth, g_Wpth);
    cudaGetSymbolAddress((void**)&Wptl, g_Wptl);
    cudaGetSymbolAddress((void**)&Fzth, g_Fzth);
    cudaGetSymbolAddress((void**)&Fztl, g_Fztl);
    cudaGetSymbolAddress((void**)&Foth, g_Foth);
    cudaGetSymbolAddress((void**)&Fotl, g_Fotl);
    cudaGetSymbolAddress((void**)&Fmth, g_Fmth);
    cudaGetSymbolAddress((void**)&Fmtl, g_Fmtl);
    cudaGetSymbolAddress((void**)&zwh, g_zwh);
    cudaGetSymbolAddress((void**)&zwl, g_zwl);
    cudaGetSymbolAddress((void**)&owh, g_owh);
    cudaGetSymbolAddress((void**)&owl, g_owl);
    cudaGetSymbolAddress((void**)&Wzth, g_Wzth);
    cudaGetSymbolAddress((void**)&Wztl, g_Wztl);
    cudaGetSymbolAddress((void**)&Wcth, g_Wcth);
    cudaGetSymbolAddress((void**)&Wctl, g_Wctl);
    cudaGetSymbolAddress((void**)&yh, g_yh);
    cudaGetSymbolAddress((void**)&yl, g_yl);

    const int M = BB * LL;
    cudaFuncSetAttribute(tgemm_kernel, cudaFuncAttributeMaxDynamicSharedMemorySize, TG_SMEM);

    dim3 tb(32, 8);

    // 1. xn = rmsnorm(x) -> hi/lo bf16
    rmsnorm_split_kernel<<<M, 256>>>(x, norm_w, xnh, xnl);

    // 2. transpose-split in_proj_W
    transpose_split_kernel<<<dim3(DD / 32, NPADPROJ / 32), tb>>>(in_proj, DD, DPROJ, Wpth, Wptl, NPADPROJ);

    // 3. zx = xn @ in_proj_W
    tgemm_kernel<<<dim3(NPADPROJ / 128, M / 128), 256, TG_SMEM>>>(xnh, xnl, Wpth, Wptl, zx, M, DPROJ, DD);

    // 4. conv + silu ; dt/dA
    {
        size_t tot = (size_t)BB * LL * CONVDIM;
        conv_kernel<<<(unsigned)((tot + 255) / 256), 256>>>(zx, conv_W, conv_b, conv);
        size_t tot2 = (size_t)BB * LL * NH;
        dtda_kernel<<<(unsigned)((tot2 + 255) / 256), 256>>>(zx, dt_bias, A_log, dt, dA);
    }

    // 5. SSM scan (128 blocks, n-split, partial outputs)
    scan_kernel<<<128, 512>>>(conv, dt, dA, y1, y2);

    // 6. side-path prep
    {
        size_t n = (size_t)DD * DIN;
        split_kernel<<<(unsigned)((n + 255) / 256), 256>>>(zero_W, zwh, zwl, n);
        split_kernel<<<(unsigned)((n + 255) / 256), 256>>>(one_W, owh, owl, n);
        transpose_split_kernel<<<dim3(DIN / 32, DD / 32), tb>>>(fusion, DIN, DD, Fmth, Fmtl, DD);
        transpose_split_kernel<<<dim3(DIN / 32, DD / 32), tb>>>(fusion + (size_t)DIN * DD, DIN, DD, Fzth, Fztl, DD);
        transpose_split_kernel<<<dim3(DIN / 32, DD / 32), tb>>>(fusion + (size_t)2 * DIN * DD, DIN, DD, Foth, Fotl, DD);
    }

    // 7. combines: Wz = zero_W @ Fz ; Wc = one_W @ Fo ; transpose-split
    tgemm_kernel<<<dim3(8, 8), 256, TG_SMEM>>>(zwh, zwl, Fzth, Fztl, Wz, DD, DD, DIN);
    tgemm_kernel<<<dim3(8, 8), 256, TG_SMEM>>>(owh, owl, Foth, Fotl, Wc, DD, DD, DIN);
    transpose_split_kernel<<<dim3(DD / 32, DD / 32), tb>>>(Wz, DD, DD, Wzth, Wztl, DD);
    transpose_split_kernel<<<dim3(DD / 32, DD / 32), tb>>>(Wc, DD, DD, Wcth, Wctl, DD);

    // 8. P = xn @ Wz ; Q = xn @ Wc
    tgemm_kernel<<<dim3(8, M / 128), 256, TG_SMEM>>>(xnh, xnl, Wzth, Wztl, P, M, DD, DD);
    tgemm_kernel<<<dim3(8, M / 128), 256, TG_SMEM>>>(xnh, xnl, Wcth, Wctl, Q, M, DD, DD);

    // 9. gated rmsnorm (merge partials + D*x) -> y hi/lo
    gnorm_split_kernel<<<M, 256>>>(y1, y2, conv, Dvec, zx, gnorm_w, yh, yl);

    // 10. R = y @ Fm
    tgemm_kernel<<<dim3(8, M / 128), 256, TG_SMEM>>>(yh, yl, Fmth, Fmtl, R, M, DD, DIN);

    // 11. cumsum + final
    chunk_sum_kernel<<<BB * NCHUNK * 4, 256>>>(Q, cs);
    scan_chunks_kernel<<<(BB * DD + 255) / 256, 256>>>(cs);
    final_kernel<<<BB * NCHUNK * 4, 256>>>(x, P, R, Q, cs, out);
}

// round 10
// speedup vs baseline: 3.3926x; 1.4736x over previous
#include <cuda_runtime.h>
#include <cuda_bf16.h>
#include <cuda_fp16.h>
#include <math.h>
#include <stdint.h>

#define BB 2
#define LL 4096
#define DD 1024
#define DIN 2048
#define DSTATE 128
#define NH 32
#define HD 64
#define CONVDIM 2304
#define DPROJ 4384
#define NPADPROJ 4480
#define NCHUNK 8
#define CHL (LL / NCHUNK)

// ---------------- scratch (device globals) ----------------
__device__ float g_zx[BB * LL * DPROJ];
__device__ float g_conv[BB * LL * CONVDIM];
__device__ float g_dt[BB * LL * NH];
__device__ float g_dA[BB * LL * NH];
__device__ float g_y1[BB * LL * DIN];   // scan partial, n in [0,64)
__device__ float g_y2[BB * LL * DIN];   // scan partial, n in [64,128)
__device__ float g_P[BB * LL * DD];
__device__ float g_Q[BB * LL * DD];
__device__ float g_R[BB * LL * DD];
__device__ float g_Wz[DD * DD];
__device__ float g_Wc[DD * DD];
__device__ float g_cs[BB * NCHUNK * DD];

__device__ __half g_xnh[BB * LL * DD];
__device__ __half g_Wpt[NPADPROJ * DD];
__device__ __half g_Fzt[DD * DIN];
__device__ __half g_Fot[DD * DIN];
__device__ __half g_Fmt[DD * DIN];
__device__ __half g_zw[DD * DIN];
__device__ __half g_ow[DD * DIN];
__device__ __half g_Wzt[DD * DD];
__device__ __half g_Wct[DD * DD];
__device__ __half g_yh[BB * LL * DIN];

// ---------------- helpers ----------------
__device__ __forceinline__ uint32_t s2u(const void* p) {
    uint32_t a;
    asm("{ .reg .u64 t; cvta.to.shared.u64 t, %1; cvt.u32.u64 %0, t; }" : "=r"(a) : "l"(p));
    return a;
}

#define LDSM4(r0, r1, r2, r3, addr)                                                         \
    asm volatile("ldmatrix.sync.aligned.m8n8.x4.shared.b16 {%0,%1,%2,%3}, [%4];"            \
                 : "=r"(r0), "=r"(r1), "=r"(r2), "=r"(r3) : "r"(addr))

#define MMA16816H(c, a, b)                                                                  \
    asm volatile("mma.sync.aligned.m16n8k16.row.col.f32.f16.f16.f32 "                       \
                 "{%0,%1,%2,%3}, {%4,%5,%6,%7}, {%8,%9}, {%0,%1,%2,%3};"                    \
                 : "+f"((c)[0]), "+f"((c)[1]), "+f"((c)[2]), "+f"((c)[3])                   \
                 : "r"((a)[0]), "r"((a)[1]), "r"((a)[2]), "r"((a)[3]),                      \
                   "r"((b)[0]), "r"((b)[1]))

__inline__ __device__ float blockReduceSum(float v) {
    __shared__ float sh[32];
    int lane = threadIdx.x & 31, wid = threadIdx.x >> 5;
#pragma unroll
    for (int o = 16; o > 0; o >>= 1) v += __shfl_down_sync(0xffffffffu, v, o);
    if (lane == 0) sh[wid] = v;
    __syncthreads();
    v = (threadIdx.x < (blockDim.x >> 5)) ? sh[lane] : 0.f;
    if (wid == 0) {
#pragma unroll
        for (int o = 16; o > 0; o >>= 1) v += __shfl_down_sync(0xffffffffu, v, o);
        if (lane == 0) sh[0] = v;
    }
    __syncthreads();
    return sh[0];
}

__inline__ __device__ float siluf(float v) { return v / (1.f + expf(-v)); }

// ---------------- rmsnorm -> fp16 ----------------
__global__ void rmsnorm_h_kernel(const float* __restrict__ x, const float* __restrict__ w,
                                 __half* __restrict__ oh) {
    size_t row = blockIdx.x;
    const float* xr = x + row * DD;
    float ss = 0.f;
    for (int i = threadIdx.x; i < DD; i += blockDim.x) { float v = xr[i]; ss += v * v; }
    ss = blockReduceSum(ss);
    float inv = rsqrtf(ss / (float)DD + 1e-5f);
    for (int i = threadIdx.x; i < DD; i += blockDim.x)
        oh[row * DD + i] = __float2half(xr[i] * inv * w[i]);
}

// ---------------- transpose -> fp16: out[n*K+k] = src[k*N+n], zero-pad to Npad ----------------
__global__ void transpose_h_kernel(const float* __restrict__ src, int K, int N,
                                   __half* __restrict__ out, int Npad) {
    __shared__ float tile[32][33];
    int k0 = blockIdx.x * 32, n0 = blockIdx.y * 32;
#pragma unroll
    for (int i = 0; i < 4; i++) {
        int k = k0 + threadIdx.y + i * 8;
        int n = n0 + threadIdx.x;
        float v = (k < K && n < N) ? src[(size_t)k * N + n] : 0.f;
        tile[threadIdx.y + i * 8][threadIdx.x] = v;
    }
    __syncthreads();
#pragma unroll
    for (int i = 0; i < 4; i++) {
        int n = n0 + threadIdx.y + i * 8;
        int k = k0 + threadIdx.x;
        if (n < Npad && k < K)
            out[(size_t)n * K + k] = __float2half(tile[threadIdx.x][threadIdx.y + i * 8]);
    }
}

// ---------------- elementwise to fp16 ----------------
__global__ void tohalf_kernel(const float* __restrict__ src, __half* __restrict__ oh, size_t n) {
    size_t i = (size_t)blockIdx.x * blockDim.x + threadIdx.x;
    if (i >= n) return;
    oh[i] = __float2half(src[i]);
}

// ---------------- fp16 single-pass mma GEMM: C[M,N] = A[M,K] @ Bt[N,K]^T ----------------
// 128x128 CTA tile, 8 warps (64x32 each), k-chunk 32, 3-stage cp.async pipeline, 2 CTAs/SM.
#define TG_STAGE_BYTES 16384
#define TG_STAGES 3
#define TG_SMEM (TG_STAGES * TG_STAGE_BYTES)

__global__ __launch_bounds__(256, 2) void tgemm_kernel(const __half* __restrict__ A,
                                                       const __half* __restrict__ B,
                                                       float* __restrict__ C, int M, int N, int K) {
    extern __shared__ char smg[];
    uint32_t sb = s2u(smg);
    const int tid = threadIdx.x;
    const int wid = tid >> 5, lid = tid & 31;
    const int m0 = blockIdx.y * 128, n0 = blockIdx.x * 128;
    const int wm = wid & 1, wn = wid >> 1;
    const int lr = lid & 15, lu = lid >> 4;
    const int NKC = K >> 5;

    // per-thread load mapping: 4 x 16B cp.async per 32-k chunk (A: 512 chunks, B: 512 chunks)
    const __half* gsrc[4];
    uint32_t dsto[4];
#pragma unroll
    for (int i = 0; i < 4; i++) {
        int q = tid + i * 256;
        int arr = q >> 9, idx = q & 511, row = idx >> 2, u = idx & 3;
        const __half* base = (arr == 0) ? A : B;
        int grow = ((arr == 0) ? m0 : n0) + row;
        gsrc[i] = base + (size_t)grow * K + u * 8;
        dsto[i] = (uint32_t)(arr * 8192 + row * 64 + ((u ^ (row & 3)) << 4));
    }

    auto issue = [&](int kc, int buf) {
        uint32_t sbuf = sb + buf * TG_STAGE_BYTES;
#pragma unroll
        for (int i = 0; i < 4; i++)
            asm volatile("cp.async.cg.shared.global [%0], [%1], 16;" ::
                         "r"(sbuf + dsto[i]), "l"((const void*)(gsrc[i] + (size_t)kc * 32))
                         : "memory");
    };

    float acc[4][4][4];
#pragma unroll
    for (int a = 0; a < 4; a++)
#pragma unroll
        for (int b = 0; b < 4; b++)
#pragma unroll
            for (int c = 0; c < 4; c++) acc[a][b][c] = 0.f;

    issue(0, 0);
    asm volatile("cp.async.commit_group;" ::: "memory");
    issue(1, 1);
    asm volatile("cp.async.commit_group;" ::: "memory");

    for (int kc = 0; kc < NKC; kc++) {
        asm volatile("cp.async.wait_group 1;" ::: "memory");
        __syncthreads();
        int nk = kc + 2;
        if (nk < NKC) issue(nk, nk % TG_STAGES);
        asm volatile("cp.async.commit_group;" ::: "memory");

        uint32_t ab = sb + (kc % TG_STAGES) * TG_STAGE_BYTES;
#pragma unroll
        for (int s = 0; s < 2; s++) {
            uint32_t af[4][4], bf[4][2];
#pragma unroll
            for (int mt = 0; mt < 4; mt++) {
                int r = wm * 64 + mt * 16 + lr;
                int u = 2 * s + lu;
                uint32_t ad = ab + r * 64 + ((u ^ (r & 3)) << 4);
                LDSM4(af[mt][0], af[mt][1], af[mt][2], af[mt][3], ad);
            }
#pragma unroll
            for (int p = 0; p < 2; p++) {
                int r = wn * 32 + p * 16 + lr;
                int u = 2 * s + lu;
                uint32_t bd = ab + 8192 + r * 64 + ((u ^ (r & 3)) << 4);
                uint32_t t0, t1, t2, t3;
                LDSM4(t0, t1, t2, t3, bd);
                bf[p * 2 + 0][0] = t0; bf[p * 2 + 0][1] = t2;
                bf[p * 2 + 1][0] = t1; bf[p * 2 + 1][1] = t3;
            }
#pragma unroll
            for (int mt = 0; mt < 4; mt++)
#pragma unroll
                for (int nt = 0; nt < 4; nt++)
                    MMA16816H(acc[mt][nt], af[mt], bf[nt]);
        }
    }

    // epilogue: direct STG
#pragma unroll
    for (int mt = 0; mt < 4; mt++) {
        int r = m0 + wm * 64 + mt * 16 + (lid >> 2);
#pragma unroll
        for (int nt = 0; nt < 4; nt++) {
            int n = n0 + wn * 32 + nt * 8 + (lid & 3) * 2;
            if (n < N) {
                *(float2*)&C[(size_t)r * N + n] = make_float2(acc[mt][nt][0], acc[mt][nt][1]);
                *(float2*)&C[(size_t)(r + 8) * N + n] = make_float2(acc[mt][nt][2], acc[mt][nt][3]);
            }
        }
    }
}

// ---------------- conv + silu ----------------
__global__ void conv_kernel(const float* __restrict__ zx, const float* __restrict__ cw,
                            const float* __restrict__ cb, float* __restrict__ out) {
    size_t idx = (size_t)blockIdx.x * blockDim.x + threadIdx.x;
    if (idx >= (size_t)BB * LL * CONVDIM) return;
    int c = idx % CONVDIM;
    size_t rest = idx / CONVDIM;
    int t = rest % LL;
    int b = rest / LL;
    float acc = cb[c];
#pragma unroll
    for (int k = 0; k < 4; k++) {
        int tt = t - 3 + k;
        if (tt >= 0)
            acc += zx[((size_t)b * LL + tt) * DPROJ + DIN + c] * cw[k * CONVDIM + c];
    }
    out[idx] = siluf(acc);
}

// ---------------- dt softplus + dA ----------------
__global__ void dtda_kernel(const float* __restrict__ zx, const float* __restrict__ dtb,
                            const float* __restrict__ alog, float* __restrict__ dtO,
                            float* __restrict__ dAO) {
    size_t idx = (size_t)blockIdx.x * blockDim.x + threadIdx.x;
    if (idx >= (size_t)BB * LL * NH) return;
    int h = idx % NH;
    size_t row = idx / NH;
    float raw = zx[row * DPROJ + (DPROJ - NH) + h] + dtb[h];
    float sp = (raw > 20.f) ? raw : log1pf(expf(raw));
    dtO[idx] = sp;
    dAO[idx] = expf(sp * (-expf(alog[h])));
}

// ---------------- SSM scan: chunked cp.async pipeline (R9-passing, unchanged) ----------------
#define SC_T 16
#define SC_NCH (LL / SC_T)

__global__ __launch_bounds__(512, 1) void scan_kernel(const float* __restrict__ conv,
                                                      const float* __restrict__ dtp,
                                                      const float* __restrict__ dAp,
                                                      float* __restrict__ yp0,
                                                      float* __restrict__ yp1) {
    const int s = blockIdx.x & 1;
    const int h = (blockIdx.x >> 1) & 31;
    const int b = blockIdx.x >> 6;
    float* __restrict__ yp = s ? yp1 : yp0;
    const int n0 = s * 64;
    const int tid = threadIdx.x;
    const int p = tid >> 3, ln = tid & 7;

    __shared__ __align__(16) float sB[3][SC_T][64];
    __shared__ __align__(16) float sC[3][SC_T][64];
    __shared__ __align__(16) float sx[3][SC_T][64];
    __shared__ float sdt[3][SC_T], sdA[3][SC_T];

    auto load = [&](int c, int st) {
#pragma unroll
        for (int q = tid; q < 800; q += 512) {
            if (q < 768) {
                int t = q / 48, k = q % 48;
                int arr = k >> 4, o = (k & 15) * 4;
                size_t g = (size_t)b * LL + (size_t)c * SC_T + t;
                const float* src;
                uint32_t d;
                if (arr == 0) { src = conv + g * CONVDIM + 2048 + n0 + o; d = s2u(&sB[st][t][o]); }
                else if (arr == 1) { src = conv + g * CONVDIM + 2176 + n0 + o; d = s2u(&sC[st][t][o]); }
                else { src = conv + g * CONVDIM + h * HD + o; d = s2u(&sx[st][t][o]); }
                asm volatile("cp.async.cg.shared.global [%0], [%1], 16;" :: "r"(d), "l"((const void*)src) : "memory");
            } else if (q < 784) {
                int t = q - 768;
                size_t g = (size_t)b * LL + (size_t)c * SC_T + t;
                uint32_t d = s2u(&sdt[st][t]);
                asm volatile("cp.async.ca.shared.global [%0], [%1], 4;" :: "r"(d), "l"((const void*)(dtp + g * NH + h)) : "memory");
            } else {
                int t = q - 784;
                size_t g = (size_t)b * LL + (size_t)c * SC_T + t;
                uint32_t d = s2u(&sdA[st][t]);
                asm volatile("cp.async.ca.shared.global [%0], [%1], 4;" :: "r"(d), "l"((const void*)(dAp + g * NH + h)) : "memory");
            }
        }
    };

    float S[8];
#pragma unroll
    for (int j = 0; j < 8; j++) S[j] = 0.f;

    load(0, 0);
    asm volatile("cp.async.commit_group;" ::: "memory");
    load(1, 1);
    asm volatile("cp.async.commit_group;" ::: "memory");

    for (int c = 0; c < SC_NCH; c++) {
        asm volatile("cp.async.wait_group 1;" ::: "memory");
        __syncthreads();
        if (c + 2 < SC_NCH) load(c + 2, (c + 2) % 3);
        asm volatile("cp.async.commit_group;" ::: "memory");

        const int st = c % 3;
        size_t gbase = ((size_t)b * LL + (size_t)c * SC_T) * DIN + h * HD + p;
#pragma unroll
        for (int t = 0; t < SC_T; t++) {
            float a = sdA[st][t];
            float dv = sdt[st][t];
            float xv = sx[st][t][p];
            float dtx = dv * xv;
            float4 b0 = *(float4*)&sB[st][t][ln * 8];
            float4 b1 = *(float4*)&sB[st][t][ln * 8 + 4];
            float4 c0 = *(float4*)&sC[st][t][ln * 8];
            float4 c1 = *(float4*)&sC[st][t][ln * 8 + 4];
            S[0] = fmaf(S[0], a, dtx * b0.x);
            S[1] = fmaf(S[1], a, dtx * b0.y);
            S[2] = fmaf(S[2], a, dtx * b0.z);
            S[3] = fmaf(S[3], a, dtx * b0.w);
            S[4] = fmaf(S[4], a, dtx * b1.x);
            S[5] = fmaf(S[5], a, dtx * b1.y);
            S[6] = fmaf(S[6], a, dtx * b1.z);
            S[7] = fmaf(S[7], a, dtx * b1.w);
            float part = S[0] * c0.x;
            part = fmaf(S[1], c0.y, part);
            part = fmaf(S[2], c0.z, part);
            part = fmaf(S[3], c0.w, part);
            part = fmaf(S[4], c1.x, part);
            part = fmaf(S[5], c1.y, part);
            part = fmaf(S[6], c1.z, part);
            part = fmaf(S[7], c1.w, part);
            part += __shfl_down_sync(0xffffffffu, part, 4, 8);
            part += __shfl_down_sync(0xffffffffu, part, 2, 8);
            part += __shfl_down_sync(0xffffffffu, part, 1, 8);
            if (ln == 0) yp[gbase + (size_t)t * DIN] = part;
        }
    }
}

// ---------------- gated rmsnorm (merges scan partials + D*x) -> fp16 ----------------
__global__ void gnorm_h_kernel(const float* __restrict__ y1, const float* __restrict__ y2,
                               const float* __restrict__ conv, const float* __restrict__ Dp,
                               const float* __restrict__ zx, const float* __restrict__ gw,
                               __half* __restrict__ oh) {
    size_t row = blockIdx.x;
    const float* zr = zx + row * DPROJ;
    float v[8];
    float ss = 0.f;
#pragma unroll
    for (int u = 0; u < 8; u++) {
        int i = threadIdx.x + u * 256;
        float xv = conv[row * CONVDIM + i];
        float yv = y1[row * DIN + i] + y2[row * DIN + i] + Dp[i >> 6] * xv;
        float z = zr[i];
        float val = yv * siluf(z);
        v[u] = val;
        ss += val * val;
    }
    ss = blockReduceSum(ss);
    float inv = rsqrtf(ss / (float)DIN + 1e-5f);
#pragma unroll
    for (int u = 0; u < 8; u++) {
        int i = threadIdx.x + u * 256;
        oh[row * DIN + i] = __float2half(v[u] * inv * gw[i]);
    }
}

// ---------------- cumsum passes ----------------
__global__ void chunk_sum_kernel(const float* __restrict__ Q, float* __restrict__ cs) {
    int c = (blockIdx.x & 3) * 256 + threadIdx.x;
    int chunk = (blockIdx.x >> 2) & (NCHUNK - 1);
    int b = blockIdx.x >> 5;
    float s = 0.f;
    size_t base = ((size_t)b * LL + (size_t)chunk * CHL) * DD + c;
    for (int l = 0; l < CHL; l++) s += Q[base + (size_t)l * DD];
    cs[((size_t)b * NCHUNK + chunk) * DD + c] = s;
}

__global__ void scan_chunks_kernel(float* __restrict__ cs) {
    int i = blockIdx.x * blockDim.x + threadIdx.x;
    if (i >= BB * DD) return;
    int b = i / DD, c = i % DD;
    float acc = 0.f;
#pragma unroll
    for (int ch = 0; ch < NCHUNK; ch++) {
        size_t o = ((size_t)b * NCHUNK + ch) * DD + c;
        float v = cs[o];
        cs[o] = acc;
        acc += v;
    }
}

__global__ void final_kernel(const float* __restrict__ x, const float* __restrict__ P,
                             const float* __restrict__ R, const float* __restrict__ Q,
                             const float* __restrict__ cs, float* __restrict__ out) {
    int c = (blockIdx.x & 3) * 256 + threadIdx.x;
    int chunk = (blockIdx.x >> 2) & (NCHUNK - 1);
    int b = blockIdx.x >> 5;
    float acc = cs[((size_t)b * NCHUNK + chunk) * DD + c];
    size_t base = ((size_t)b * LL + (size_t)chunk * CHL) * DD + c;
    for (int l = 0; l < CHL; l++) {
        size_t idx = base + (size_t)l * DD;
        acc += Q[idx];
        out[idx] = x[idx] + P[idx] + R[idx] + acc;
    }
}

// ---------------- launch ----------------
extern "C" void kernel_launch(void* const* d_in, const int* in_sizes, int n_in,
                              void* d_out, int out_size) {
    const float* x       = (const float*)d_in[0];
    const float* norm_w  = (const float*)d_in[1];
    const float* in_proj = (const float*)d_in[2];
    const float* conv_W  = (const float*)d_in[3];
    const float* conv_b  = (const float*)d_in[4];
    const float* dt_bias = (const float*)d_in[5];
    const float* A_log   = (const float*)d_in[6];
    const float* Dvec    = (const float*)d_in[7];
    const float* gnorm_w = (const float*)d_in[8];
    const float* zero_W  = (const float*)d_in[9];
    const float* one_W   = (const float*)d_in[10];
    const float* fusion  = (const float*)d_in[11];
    float* out = (float*)d_out;

    float *zx, *conv, *dt, *dA, *y1, *y2, *P, *Q, *R, *Wz, *Wc, *cs;
    __half *xnh, *Wpt, *Fzt, *Fot, *Fmt, *zw, *ow, *Wzt, *Wct, *yh;
    cudaGetSymbolAddress((void**)&zx, g_zx);
    cudaGetSymbolAddress((void**)&conv, g_conv);
    cudaGetSymbolAddress((void**)&dt, g_dt);
    cudaGetSymbolAddress((void**)&dA, g_dA);
    cudaGetSymbolAddress((void**)&y1, g_y1);
    cudaGetSymbolAddress((void**)&y2, g_y2);
    cudaGetSymbolAddress((void**)&P, g_P);
    cudaGetSymbolAddress((void**)&Q, g_Q);
    cudaGetSymbolAddress((void**)&R, g_R);
    cudaGetSymbolAddress((void**)&Wz, g_Wz);
    cudaGetSymbolAddress((void**)&Wc, g_Wc);
    cudaGetSymbolAddress((void**)&cs, g_cs);
    cudaGetSymbolAddress((void**)&xnh, g_xnh);
    cudaGetSymbolAddress((void**)&Wpt, g_Wpt);
    cudaGetSymbolAddress((void**)&Fzt, g_Fzt);
    cudaGetSymbolAddress((void**)&Fot, g_Fot);
    cudaGetSymbolAddress((void**)&Fmt, g_Fmt);
    cudaGetSymbolAddress((void**)&zw, g_zw);
    cudaGetSymbolAddress((void**)&ow, g_ow);
    cudaGetSymbolAddress((void**)&Wzt, g_Wzt);
    cudaGetSymbolAddress((void**)&Wct, g_Wct);
    cudaGetSymbolAddress((void**)&yh, g_yh);

    const int M = BB * LL;
    cudaFuncSetAttribute(tgemm_kernel, cudaFuncAttributeMaxDynamicSharedMemorySize, TG_SMEM);

    dim3 tb(32, 8);

    // 1. xn = rmsnorm(x) -> fp16
    rmsnorm_h_kernel<<<M, 256>>>(x, norm_w, xnh);

    // 2. transpose in_proj_W -> fp16 [4480,1024]
    transpose_h_kernel<<<dim3(DD / 32, NPADPROJ / 32), tb>>>(in_proj, DD, DPROJ, Wpt, NPADPROJ);

    // 3. zx = xn @ in_proj_W
    tgemm_kernel<<<dim3(NPADPROJ / 128, M / 128), 256, TG_SMEM>>>(xnh, Wpt, zx, M, DPROJ, DD);

    // 4. conv + silu ; dt/dA
    {
        size_t tot = (size_t)BB * LL * CONVDIM;
        conv_kernel<<<(unsigned)((tot + 255) / 256), 256>>>(zx, conv_W, conv_b, conv);
        size_t tot2 = (size_t)BB * LL * NH;
        dtda_kernel<<<(unsigned)((tot2 + 255) / 256), 256>>>(zx, dt_bias, A_log, dt, dA);
    }

    // 5. SSM scan (128 blocks, n-split, partial outputs)
    scan_kernel<<<128, 512>>>(conv, dt, dA, y1, y2);

    // 6. side-path prep
    {
        size_t n = (size_t)DD * DIN;
        tohalf_kernel<<<(unsigned)((n + 255) / 256), 256>>>(zero_W, zw, n);
        tohalf_kernel<<<(unsigned)((n + 255) / 256), 256>>>(one_W, ow, n);
        transpose_h_kernel<<<dim3(DIN / 32, DD / 32), tb>>>(fusion, DIN, DD, Fmt, DD);
        transpose_h_kernel<<<dim3(DIN / 32, DD / 32), tb>>>(fusion + (size_t)DIN * DD, DIN, DD, Fzt, DD);
        transpose_h_kernel<<<dim3(DIN / 32, DD / 32), tb>>>(fusion + (size_t)2 * DIN * DD, DIN, DD, Fot, DD);
    }

    // 7. combines: Wz = zero_W @ Fz ; Wc = one_W @ Fo ; transpose to fp16
    tgemm_kernel<<<dim3(8, 8), 256, TG_SMEM>>>(zw, Fzt, Wz, DD, DD, DIN);
    tgemm_kernel<<<dim3(8, 8), 256, TG_SMEM>>>(ow, Fot, Wc, DD, DD, DIN);
    transpose_h_kernel<<<dim3(DD / 32, DD / 32), tb>>>(Wz, DD, DD, Wzt, DD);
    transpose_h_kernel<<<dim3(DD / 32, DD / 32), tb>>>(Wc, DD, DD, Wct, DD);

    // 8. P = xn @ Wz ; Q = xn @ Wc
    tgemm_kernel<<<dim3(8, M / 128), 256, TG_SMEM>>>(xnh, Wzt, P, M, DD, DD);
    tgemm_kernel<<<dim3(8, M / 128), 256, TG_SMEM>>>(xnh, Wct, Q, M, DD, DD);

    // 9. gated rmsnorm (merge partials + D*x) -> y fp16
    gnorm_h_kernel<<<M, 256>>>(y1, y2, conv, Dvec, zx, gnorm_w, yh);

    // 10. R = y @ Fm
    tgemm_kernel<<<dim3(8, M / 128), 256, TG_SMEM>>>(yh, Fmt, R, M, DD, DIN);

    // 11. cumsum + final
    chunk_sum_kernel<<<BB * NCHUNK * 4, 256>>>(Q, cs);
    scan_chunks_kernel<<<(BB * DD + 255) / 256, 256>>>(cs);
    final_kernel<<<BB * NCHUNK * 4, 256>>>(x, P, R, Q, cs, out);
}

// round 11
// speedup vs baseline: 3.4464x; 1.0159x over previous
#include <cuda_runtime.h>
#include <cuda_bf16.h>
#include <cuda_fp16.h>
#include <math.h>
#include <stdint.h>

#define BB 2
#define LL 4096
#define DD 1024
#define DIN 2048
#define DSTATE 128
#define NH 32
#define HD 64
#define CONVDIM 2304
#define DPROJ 4384
#define NPADPROJ 4480
#define NCHUNK 8
#define CHL (LL / NCHUNK)

// ---------------- scratch (device globals) ----------------
__device__ float g_zx[BB * LL * DPROJ];
__device__ float g_conv[BB * LL * CONVDIM];
__device__ float g_dt[BB * LL * NH];
__device__ float g_dA[BB * LL * NH];
__device__ float g_y1[BB * LL * DIN];   // scan partial, n in [0,64)
__device__ float g_y2[BB * LL * DIN];   // scan partial, n in [64,128)
__device__ float g_PQ[BB * LL * 2 * DD];  // [row][0:1024]=P, [1024:2048]=Q
__device__ float g_R[BB * LL * DD];
__device__ float g_Wz[DD * DD];
__device__ float g_Wc[DD * DD];
__device__ float g_cs[BB * NCHUNK * DD];

__device__ __half g_xnh[BB * LL * DD];
__device__ __half g_Wpt[NPADPROJ * DD];
__device__ __half g_Fzt[DD * DIN];
__device__ __half g_Fot[DD * DIN];
__device__ __half g_Fmt[DD * DIN];
__device__ __half g_zw[DD * DIN];
__device__ __half g_ow[DD * DIN];
__device__ __half g_Wpq[2 * DD * DD];   // rows 0..1023 = Wz^T, rows 1024..2047 = Wc^T
__device__ __half g_yh[BB * LL * DIN];

// ---------------- helpers ----------------
__device__ __forceinline__ uint32_t s2u(const void* p) {
    uint32_t a;
    asm("{ .reg .u64 t; cvta.to.shared.u64 t, %1; cvt.u32.u64 %0, t; }" : "=r"(a) : "l"(p));
    return a;
}

#define LDSM4(r0, r1, r2, r3, addr)                                                         \
    asm volatile("ldmatrix.sync.aligned.m8n8.x4.shared.b16 {%0,%1,%2,%3}, [%4];"            \
                 : "=r"(r0), "=r"(r1), "=r"(r2), "=r"(r3) : "r"(addr))

#define MMA16816H(c, a, b)                                                                  \
    asm volatile("mma.sync.aligned.m16n8k16.row.col.f32.f16.f16.f32 "                       \
                 "{%0,%1,%2,%3}, {%4,%5,%6,%7}, {%8,%9}, {%0,%1,%2,%3};"                    \
                 : "+f"((c)[0]), "+f"((c)[1]), "+f"((c)[2]), "+f"((c)[3])                   \
                 : "r"((a)[0]), "r"((a)[1]), "r"((a)[2]), "r"((a)[3]),                      \
                   "r"((b)[0]), "r"((b)[1]))

__inline__ __device__ float blockReduceSum(float v) {
    __shared__ float sh[32];
    int lane = threadIdx.x & 31, wid = threadIdx.x >> 5;
#pragma unroll
    for (int o = 16; o > 0; o >>= 1) v += __shfl_down_sync(0xffffffffu, v, o);
    if (lane == 0) sh[wid] = v;
    __syncthreads();
    v = (threadIdx.x < (blockDim.x >> 5)) ? sh[lane] : 0.f;
    if (wid == 0) {
#pragma unroll
        for (int o = 16; o > 0; o >>= 1) v += __shfl_down_sync(0xffffffffu, v, o);
        if (lane == 0) sh[0] = v;
    }
    __syncthreads();
    return sh[0];
}

__inline__ __device__ float siluf(float v) { return v / (1.f + expf(-v)); }

// ---------------- rmsnorm -> fp16 ----------------
__global__ void rmsnorm_h_kernel(const float* __restrict__ x, const float* __restrict__ w,
                                 __half* __restrict__ oh) {
    size_t row = blockIdx.x;
    const float* xr = x + row * DD;
    float ss = 0.f;
    for (int i = threadIdx.x; i < DD; i += blockDim.x) { float v = xr[i]; ss += v * v; }
    ss = blockReduceSum(ss);
    float inv = rsqrtf(ss / (float)DD + 1e-5f);
    for (int i = threadIdx.x; i < DD; i += blockDim.x)
        oh[row * DD + i] = __float2half(xr[i] * inv * w[i]);
}

// ---------------- transpose -> fp16: out[n*K+k] = src[k*N+n], zero-pad to Npad ----------------
__global__ void transpose_h_kernel(const float* __restrict__ src, int K, int N,
                                   __half* __restrict__ out, int Npad) {
    __shared__ float tile[32][33];
    int k0 = blockIdx.x * 32, n0 = blockIdx.y * 32;
#pragma unroll
    for (int i = 0; i < 4; i++) {
        int k = k0 + threadIdx.y + i * 8;
        int n = n0 + threadIdx.x;
        float v = (k < K && n < N) ? src[(size_t)k * N + n] : 0.f;
        tile[threadIdx.y + i * 8][threadIdx.x] = v;
    }
    __syncthreads();
#pragma unroll
    for (int i = 0; i < 4; i++) {
        int n = n0 + threadIdx.y + i * 8;
        int k = k0 + threadIdx.x;
        if (n < Npad && k < K)
            out[(size_t)n * K + k] = __float2half(tile[threadIdx.x][threadIdx.y + i * 8]);
    }
}

// ---------------- elementwise to fp16 ----------------
__global__ void tohalf_kernel(const float* __restrict__ src, __half* __restrict__ oh, size_t n) {
    size_t i = (size_t)blockIdx.x * blockDim.x + threadIdx.x;
    if (i >= n) return;
    oh[i] = __float2half(src[i]);
}

// ---------------- fp16 single-pass mma GEMM: C[M,N] = A[M,K] @ Bt[N,K]^T ----------------
// 128x128 CTA tile, 8 warps (64x32 each), k-chunk 32, 4-stage cp.async pipeline, 2 CTAs/SM.
#define TG_STAGE_BYTES 16384
#define TG_STAGES 4
#define TG_SMEM (TG_STAGES * TG_STAGE_BYTES)

__global__ __launch_bounds__(256, 2) void tgemm_kernel(const __half* __restrict__ A,
                                                       const __half* __restrict__ B,
                                                       float* __restrict__ C, int M, int N, int K) {
    extern __shared__ char smg[];
    uint32_t sb = s2u(smg);
    const int tid = threadIdx.x;
    const int wid = tid >> 5, lid = tid & 31;
    const int m0 = blockIdx.y * 128, n0 = blockIdx.x * 128;
    const int wm = wid & 1, wn = wid >> 1;
    const int lr = lid & 15, lu = lid >> 4;
    const int NKC = K >> 5;

    // per-thread load mapping: 4 x 16B cp.async per 32-k chunk
    const __half* gsrc[4];
    uint32_t dsto[4];
#pragma unroll
    for (int i = 0; i < 4; i++) {
        int q = tid + i * 256;
        int arr = q >> 9, idx = q & 511, row = idx >> 2, u = idx & 3;
        const __half* base = (arr == 0) ? A : B;
        int grow = ((arr == 0) ? m0 : n0) + row;
        gsrc[i] = base + (size_t)grow * K + u * 8;
        dsto[i] = (uint32_t)(arr * 8192 + row * 64 + ((u ^ (row & 3)) << 4));
    }

    auto issue = [&](int kc, int buf) {
        uint32_t sbuf = sb + buf * TG_STAGE_BYTES;
#pragma unroll
        for (int i = 0; i < 4; i++)
            asm volatile("cp.async.cg.shared.global [%0], [%1], 16;" ::
                         "r"(sbuf + dsto[i]), "l"((const void*)(gsrc[i] + (size_t)kc * 32))
                         : "memory");
    };

    float acc[4][4][4];
#pragma unroll
    for (int a = 0; a < 4; a++)
#pragma unroll
        for (int b = 0; b < 4; b++)
#pragma unroll
            for (int c = 0; c < 4; c++) acc[a][b][c] = 0.f;

    issue(0, 0);
    asm volatile("cp.async.commit_group;" ::: "memory");
    issue(1, 1);
    asm volatile("cp.async.commit_group;" ::: "memory");
    issue(2, 2);
    asm volatile("cp.async.commit_group;" ::: "memory");

    for (int kc = 0; kc < NKC; kc++) {
        asm volatile("cp.async.wait_group 2;" ::: "memory");
        __syncthreads();
        int nk = kc + 3;
        if (nk < NKC) issue(nk, nk & 3);
        asm volatile("cp.async.commit_group;" ::: "memory");

        uint32_t ab = sb + (kc & 3) * TG_STAGE_BYTES;
#pragma unroll
        for (int s = 0; s < 2; s++) {
            uint32_t af[4][4], bf[4][2];
#pragma unroll
            for (int mt = 0; mt < 4; mt++) {
                int r = wm * 64 + mt * 16 + lr;
                int u = 2 * s + lu;
                uint32_t ad = ab + r * 64 + ((u ^ (r & 3)) << 4);
                LDSM4(af[mt][0], af[mt][1], af[mt][2], af[mt][3], ad);
            }
#pragma unroll
            for (int p = 0; p < 2; p++) {
                int r = wn * 32 + p * 16 + lr;
                int u = 2 * s + lu;
                uint32_t bd = ab + 8192 + r * 64 + ((u ^ (r & 3)) << 4);
                uint32_t t0, t1, t2, t3;
                LDSM4(t0, t1, t2, t3, bd);
                bf[p * 2 + 0][0] = t0; bf[p * 2 + 0][1] = t2;
                bf[p * 2 + 1][0] = t1; bf[p * 2 + 1][1] = t3;
            }
#pragma unroll
            for (int mt = 0; mt < 4; mt++)
#pragma unroll
                for (int nt = 0; nt < 4; nt++)
                    MMA16816H(acc[mt][nt], af[mt], bf[nt]);
        }
    }

    // epilogue: direct STG
#pragma unroll
    for (int mt = 0; mt < 4; mt++) {
        int r = m0 + wm * 64 + mt * 16 + (lid >> 2);
#pragma unroll
        for (int nt = 0; nt < 4; nt++) {
            int n = n0 + wn * 32 + nt * 8 + (lid & 3) * 2;
            if (n < N) {
                *(float2*)&C[(size_t)r * N + n] = make_float2(acc[mt][nt][0], acc[mt][nt][1]);
                *(float2*)&C[(size_t)(r + 8) * N + n] = make_float2(acc[mt][nt][2], acc[mt][nt][3]);
            }
        }
    }
}

// ---------------- conv + silu ----------------
__global__ void conv_kernel(const float* __restrict__ zx, const float* __restrict__ cw,
                            const float* __restrict__ cb, float* __restrict__ out) {
    size_t idx = (size_t)blockIdx.x * blockDim.x + threadIdx.x;
    if (idx >= (size_t)BB * LL * CONVDIM) return;
    int c = idx % CONVDIM;
    size_t rest = idx / CONVDIM;
    int t = rest % LL;
    int b = rest / LL;
    float acc = cb[c];
#pragma unroll
    for (int k = 0; k < 4; k++) {
        int tt = t - 3 + k;
        if (tt >= 0)
            acc += zx[((size_t)b * LL + tt) * DPROJ + DIN + c] * cw[k * CONVDIM + c];
    }
    out[idx] = siluf(acc);
}

// ---------------- dt softplus + dA ----------------
__global__ void dtda_kernel(const float* __restrict__ zx, const float* __restrict__ dtb,
                            const float* __restrict__ alog, float* __restrict__ dtO,
                            float* __restrict__ dAO) {
    size_t idx = (size_t)blockIdx.x * blockDim.x + threadIdx.x;
    if (idx >= (size_t)BB * LL * NH) return;
    int h = idx % NH;
    size_t row = idx / NH;
    float raw = zx[row * DPROJ + (DPROJ - NH) + h] + dtb[h];
    float sp = (raw > 20.f) ? raw : log1pf(expf(raw));
    dtO[idx] = sp;
    dAO[idx] = expf(sp * (-expf(alog[h])));
}

// ---------------- SSM scan: chunked cp.async pipeline (R9/R10-passing, unchanged) ----------------
#define SC_T 16
#define SC_NCH (LL / SC_T)

__global__ __launch_bounds__(512, 1) void scan_kernel(const float* __restrict__ conv,
                                                      const float* __restrict__ dtp,
                                                      const float* __restrict__ dAp,
                                                      float* __restrict__ yp0,
                                                      float* __restrict__ yp1) {
    const int s = blockIdx.x & 1;
    const int h = (blockIdx.x >> 1) & 31;
    const int b = blockIdx.x >> 6;
    float* __restrict__ yp = s ? yp1 : yp0;
    const int n0 = s * 64;
    const int tid = threadIdx.x;
    const int p = tid >> 3, ln = tid & 7;

    __shared__ __align__(16) float sB[3][SC_T][64];
    __shared__ __align__(16) float sC[3][SC_T][64];
    __shared__ __align__(16) float sx[3][SC_T][64];
    __shared__ float sdt[3][SC_T], sdA[3][SC_T];

    auto load = [&](int c, int st) {
#pragma unroll
        for (int q = tid; q < 800; q += 512) {
            if (q < 768) {
                int t = q / 48, k = q % 48;
                int arr = k >> 4, o = (k & 15) * 4;
                size_t g = (size_t)b * LL + (size_t)c * SC_T + t;
                const float* src;
                uint32_t d;
                if (arr == 0) { src = conv + g * CONVDIM + 2048 + n0 + o; d = s2u(&sB[st][t][o]); }
                else if (arr == 1) { src = conv + g * CONVDIM + 2176 + n0 + o; d = s2u(&sC[st][t][o]); }
                else { src = conv + g * CONVDIM + h * HD + o; d = s2u(&sx[st][t][o]); }
                asm volatile("cp.async.cg.shared.global [%0], [%1], 16;" :: "r"(d), "l"((const void*)src) : "memory");
            } else if (q < 784) {
                int t = q - 768;
                size_t g = (size_t)b * LL + (size_t)c * SC_T + t;
                uint32_t d = s2u(&sdt[st][t]);
                asm volatile("cp.async.ca.shared.global [%0], [%1], 4;" :: "r"(d), "l"((const void*)(dtp + g * NH + h)) : "memory");
            } else {
                int t = q - 784;
                size_t g = (size_t)b * LL + (size_t)c * SC_T + t;
                uint32_t d = s2u(&sdA[st][t]);
                asm volatile("cp.async.ca.shared.global [%0], [%1], 4;" :: "r"(d), "l"((const void*)(dAp + g * NH + h)) : "memory");
            }
        }
    };

    float S[8];
#pragma unroll
    for (int j = 0; j < 8; j++) S[j] = 0.f;

    load(0, 0);
    asm volatile("cp.async.commit_group;" ::: "memory");
    load(1, 1);
    asm volatile("cp.async.commit_group;" ::: "memory");

    for (int c = 0; c < SC_NCH; c++) {
        asm volatile("cp.async.wait_group 1;" ::: "memory");
        __syncthreads();
        if (c + 2 < SC_NCH) load(c + 2, (c + 2) % 3);
        asm volatile("cp.async.commit_group;" ::: "memory");

        const int st = c % 3;
        size_t gbase = ((size_t)b * LL + (size_t)c * SC_T) * DIN + h * HD + p;
#pragma unroll
        for (int t = 0; t < SC_T; t++) {
            float a = sdA[st][t];
            float dv = sdt[st][t];
            float xv = sx[st][t][p];
            float dtx = dv * xv;
            float4 b0 = *(float4*)&sB[st][t][ln * 8];
            float4 b1 = *(float4*)&sB[st][t][ln * 8 + 4];
            float4 c0 = *(float4*)&sC[st][t][ln * 8];
            float4 c1 = *(float4*)&sC[st][t][ln * 8 + 4];
            S[0] = fmaf(S[0], a, dtx * b0.x);
            S[1] = fmaf(S[1], a, dtx * b0.y);
            S[2] = fmaf(S[2], a, dtx * b0.z);
            S[3] = fmaf(S[3], a, dtx * b0.w);
            S[4] = fmaf(S[4], a, dtx * b1.x);
            S[5] = fmaf(S[5], a, dtx * b1.y);
            S[6] = fmaf(S[6], a, dtx * b1.z);
            S[7] = fmaf(S[7], a, dtx * b1.w);
            float part = S[0] * c0.x;
            part = fmaf(S[1], c0.y, part);
            part = fmaf(S[2], c0.z, part);
            part = fmaf(S[3], c0.w, part);
            part = fmaf(S[4], c1.x, part);
            part = fmaf(S[5], c1.y, part);
            part = fmaf(S[6], c1.z, part);
            part = fmaf(S[7], c1.w, part);
            part += __shfl_down_sync(0xffffffffu, part, 4, 8);
            part += __shfl_down_sync(0xffffffffu, part, 2, 8);
            part += __shfl_down_sync(0xffffffffu, part, 1, 8);
            if (ln == 0) yp[gbase + (size_t)t * DIN] = part;
        }
    }
}

// ---------------- gated rmsnorm (merges scan partials + D*x) -> fp16 ----------------
__global__ void gnorm_h_kernel(const float* __restrict__ y1, const float* __restrict__ y2,
                               const float* __restrict__ conv, const float* __restrict__ Dp,
                               const float* __restrict__ zx, const float* __restrict__ gw,
                               __half* __restrict__ oh) {
    size_t row = blockIdx.x;
    const float* zr = zx + row * DPROJ;
    float v[8];
    float ss = 0.f;
#pragma unroll
    for (int u = 0; u < 8; u++) {
        int i = threadIdx.x + u * 256;
        float xv = conv[row * CONVDIM + i];
        float yv = y1[row * DIN + i] + y2[row * DIN + i] + Dp[i >> 6] * xv;
        float z = zr[i];
        float val = yv * siluf(z);
        v[u] = val;
        ss += val * val;
    }
    ss = blockReduceSum(ss);
    float inv = rsqrtf(ss / (float)DIN + 1e-5f);
#pragma unroll
    for (int u = 0; u < 8; u++) {
        int i = threadIdx.x + u * 256;
        oh[row * DIN + i] = __float2half(v[u] * inv * gw[i]);
    }
}

// ---------------- cumsum passes (over Q = PQ[:,1024:2048]) ----------------
__global__ void chunk_sum_kernel(const float* __restrict__ PQ, float* __restrict__ cs) {
    int c = (blockIdx.x & 3) * 256 + threadIdx.x;
    int chunk = (blockIdx.x >> 2) & (NCHUNK - 1);
    int b = blockIdx.x >> 5;
    float s = 0.f;
    size_t base = ((size_t)b * LL + (size_t)chunk * CHL) * (2 * DD) + DD + c;
    for (int l = 0; l < CHL; l++) s += PQ[base + (size_t)l * (2 * DD)];
    cs[((size_t)b * NCHUNK + chunk) * DD + c] = s;
}

__global__ void scan_chunks_kernel(float* __restrict__ cs) {
    int i = blockIdx.x * blockDim.x + threadIdx.x;
    if (i >= BB * DD) return;
    int b = i / DD, c = i % DD;
    float acc = 0.f;
#pragma unroll
    for (int ch = 0; ch < NCHUNK; ch++) {
        size_t o = ((size_t)b * NCHUNK + ch) * DD + c;
        float v = cs[o];
        cs[o] = acc;
        acc += v;
    }
}

__global__ void final_kernel(const float* __restrict__ x, const float* __restrict__ PQ,
                             const float* __restrict__ R,
                             const float* __restrict__ cs, float* __restrict__ out) {
    int c = (blockIdx.x & 3) * 256 + threadIdx.x;
    int chunk = (blockIdx.x >> 2) & (NCHUNK - 1);
    int b = blockIdx.x >> 5;
    float acc = cs[((size_t)b * NCHUNK + chunk) * DD + c];
    size_t rbase = ((size_t)b * LL + (size_t)chunk * CHL) * DD + c;
    size_t pqbase = ((size_t)b * LL + (size_t)chunk * CHL) * (2 * DD) + c;
    for (int l = 0; l < CHL; l++) {
        size_t idx = rbase + (size_t)l * DD;
        size_t pqi = pqbase + (size_t)l * (2 * DD);
        acc += PQ[pqi + DD];
        out[idx] = x[idx] + PQ[pqi] + R[idx] + acc;
    }
}

// ---------------- launch ----------------
extern "C" void kernel_launch(void* const* d_in, const int* in_sizes, int n_in,
                              void* d_out, int out_size) {
    const float* x       = (const float*)d_in[0];
    const float* norm_w  = (const float*)d_in[1];
    const float* in_proj = (const float*)d_in[2];
    const float* conv_W  = (const float*)d_in[3];
    const float* conv_b  = (const float*)d_in[4];
    const float* dt_bias = (const float*)d_in[5];
    const float* A_log   = (const float*)d_in[6];
    const float* Dvec    = (const float*)d_in[7];
    const float* gnorm_w = (const float*)d_in[8];
    const float* zero_W  = (const float*)d_in[9];
    const float* one_W   = (const float*)d_in[10];
    const float* fusion  = (const float*)d_in[11];
    float* out = (float*)d_out;

    float *zx, *conv, *dt, *dA, *y1, *y2, *PQ, *R, *Wz, *Wc, *cs;
    __half *xnh, *Wpt, *Fzt, *Fot, *Fmt, *zw, *ow, *Wpq, *yh;
    cudaGetSymbolAddress((void**)&zx, g_zx);
    cudaGetSymbolAddress((void**)&conv, g_conv);
    cudaGetSymbolAddress((void**)&dt, g_dt);
    cudaGetSymbolAddress((void**)&dA, g_dA);
    cudaGetSymbolAddress((void**)&y1, g_y1);
    cudaGetSymbolAddress((void**)&y2, g_y2);
    cudaGetSymbolAddress((void**)&PQ, g_PQ);
    cudaGetSymbolAddress((void**)&R, g_R);
    cudaGetSymbolAddress((void**)&Wz, g_Wz);
    cudaGetSymbolAddress((void**)&Wc, g_Wc);
    cudaGetSymbolAddress((void**)&cs, g_cs);
    cudaGetSymbolAddress((void**)&xnh, g_xnh);
    cudaGetSymbolAddress((void**)&Wpt, g_Wpt);
    cudaGetSymbolAddress((void**)&Fzt, g_Fzt);
    cudaGetSymbolAddress((void**)&Fot, g_Fot);
    cudaGetSymbolAddress((void**)&Fmt, g_Fmt);
    cudaGetSymbolAddress((void**)&zw, g_zw);
    cudaGetSymbolAddress((void**)&ow, g_ow);
    cudaGetSymbolAddress((void**)&Wpq, g_Wpq);
    cudaGetSymbolAddress((void**)&yh, g_yh);

    const int M = BB * LL;
    cudaFuncSetAttribute(tgemm_kernel, cudaFuncAttributeMaxDynamicSharedMemorySize, TG_SMEM);

    dim3 tb(32, 8);

    // 1. xn = rmsnorm(x) -> fp16
    rmsnorm_h_kernel<<<M, 256>>>(x, norm_w, xnh);

    // 2. transpose in_proj_W -> fp16 [4480,1024]
    transpose_h_kernel<<<dim3(DD / 32, NPADPROJ / 32), tb>>>(in_proj, DD, DPROJ, Wpt, NPADPROJ);

    // 3. zx = xn @ in_proj_W
    tgemm_kernel<<<dim3(NPADPROJ / 128, M / 128), 256, TG_SMEM>>>(xnh, Wpt, zx, M, DPROJ, DD);

    // 4. conv + silu ; dt/dA
    {
        size_t tot = (size_t)BB * LL * CONVDIM;
        conv_kernel<<<(unsigned)((tot + 255) / 256), 256>>>(zx, conv_W, conv_b, conv);
        size_t tot2 = (size_t)BB * LL * NH;
        dtda_kernel<<<(unsigned)((tot2 + 255) / 256), 256>>>(zx, dt_bias, A_log, dt, dA);
    }

    // 5. SSM scan (128 blocks, n-split, partial outputs)
    scan_kernel<<<128, 512>>>(conv, dt, dA, y1, y2);

    // 6. side-path prep
    {
        size_t n = (size_t)DD * DIN;
        tohalf_kernel<<<(unsigned)((n + 255) / 256), 256>>>(zero_W, zw, n);
        tohalf_kernel<<<(unsigned)((n + 255) / 256), 256>>>(one_W, ow, n);
        transpose_h_kernel<<<dim3(DIN / 32, DD / 32), tb>>>(fusion, DIN, DD, Fmt, DD);
        transpose_h_kernel<<<dim3(DIN / 32, DD / 32), tb>>>(fusion + (size_t)DIN * DD, DIN, DD, Fzt, DD);
        transpose_h_kernel<<<dim3(DIN / 32, DD / 32), tb>>>(fusion + (size_t)2 * DIN * DD, DIN, DD, Fot, DD);
    }

    // 7. combines: Wz = zero_W @ Fz ; Wc = one_W @ Fo ; transpose into concatenated [Wz^T | Wc^T]
    tgemm_kernel<<<dim3(8, 8), 256, TG_SMEM>>>(zw, Fzt, Wz, DD, DD, DIN);
    tgemm_kernel<<<dim3(8, 8), 256, TG_SMEM>>>(ow, Fot, Wc, DD, DD, DIN);
    transpose_h_kernel<<<dim3(DD / 32, DD / 32), tb>>>(Wz, DD, DD, Wpq, DD);
    transpose_h_kernel<<<dim3(DD / 32, DD / 32), tb>>>(Wc, DD, DD, Wpq + (size_t)DD * DD, DD);

    // 8. PQ = xn @ [Wz | Wc]  (single N=2048 GEMM)
    tgemm_kernel<<<dim3(16, M / 128), 256, TG_SMEM>>>(xnh, Wpq, PQ, M, 2 * DD, DD);

    // 9. gated rmsnorm (merge partials + D*x) -> y fp16
    gnorm_h_kernel<<<M, 256>>>(y1, y2, conv, Dvec, zx, gnorm_w, yh);

    // 10. R = y @ Fm
    tgemm_kernel<<<dim3(8, M / 128), 256, TG_SMEM>>>(yh, Fmt, R, M, DD, DIN);

    // 11. cumsum + final
    chunk_sum_kernel<<<BB * NCHUNK * 4, 256>>>(PQ, cs);
    scan_chunks_kernel<<<(BB * DD + 255) / 256, 256>>>(cs);
    final_kernel<<<BB * NCHUNK * 4, 256>>>(x, PQ, R, cs, out);
}

// round 12
// speedup vs baseline: 3.7920x; 1.1003x over previous
#include <cuda_runtime.h>
#include <cuda_bf16.h>
#include <cuda_fp16.h>
#include <math.h>
#include <stdint.h>

#define BB 2
#define LL 4096
#define DD 1024
#define DIN 2048
#define DSTATE 128
#define NH 32
#define HD 64
#define CONVDIM 2304
#define DPROJ 4384
#define NPADPROJ 4480
#define NCHUNK 8
#define CHL (LL / NCHUNK)

// ---------------- scratch (device globals) ----------------
__device__ float g_zx[BB * LL * DPROJ];
__device__ float g_conv[BB * LL * CONVDIM];
__device__ float g_dt[BB * LL * NH];
__device__ float g_dA[BB * LL * NH];
__device__ float g_y1[BB * LL * DIN];
__device__ float g_y2[BB * LL * DIN];
__device__ float g_PQ[BB * LL * 2 * DD];  // [row][0:1024]=P, [1024:2048]=Q
__device__ float g_R[BB * LL * DD];
__device__ float g_Wz[DD * DD];
__device__ float g_Wc[DD * DD];
__device__ float g_cs[BB * NCHUNK * DD];

__device__ __half g_xnh[BB * LL * DD];
__device__ __half g_Wpt[NPADPROJ * DD];
__device__ __half g_Fzt[DD * DIN];
__device__ __half g_Fot[DD * DIN];
__device__ __half g_Fmt[DD * DIN];
__device__ __half g_zw[DD * DIN];
__device__ __half g_ow[DD * DIN];
__device__ __half g_Wpq[2 * DD * DD];
__device__ __half g_yh[BB * LL * DIN];

// ---------------- helpers ----------------
__device__ __forceinline__ uint32_t s2u(const void* p) {
    uint32_t a;
    asm("{ .reg .u64 t; cvta.to.shared.u64 t, %1; cvt.u32.u64 %0, t; }" : "=r"(a) : "l"(p));
    return a;
}

#define LDSM4(r0, r1, r2, r3, addr)                                                         \
    asm volatile("ldmatrix.sync.aligned.m8n8.x4.shared.b16 {%0,%1,%2,%3}, [%4];"            \
                 : "=r"(r0), "=r"(r1), "=r"(r2), "=r"(r3) : "r"(addr))

#define MMA16816H(c, a, b)                                                                  \
    asm volatile("mma.sync.aligned.m16n8k16.row.col.f32.f16.f16.f32 "                       \
                 "{%0,%1,%2,%3}, {%4,%5,%6,%7}, {%8,%9}, {%0,%1,%2,%3};"                    \
                 : "+f"((c)[0]), "+f"((c)[1]), "+f"((c)[2]), "+f"((c)[3])                   \
                 : "r"((a)[0]), "r"((a)[1]), "r"((a)[2]), "r"((a)[3]),                      \
                   "r"((b)[0]), "r"((b)[1]))

__inline__ __device__ float blockReduceSum(float v) {
    __shared__ float sh[32];
    int lane = threadIdx.x & 31, wid = threadIdx.x >> 5;
#pragma unroll
    for (int o = 16; o > 0; o >>= 1) v += __shfl_down_sync(0xffffffffu, v, o);
    if (lane == 0) sh[wid] = v;
    __syncthreads();
    v = (threadIdx.x < (blockDim.x >> 5)) ? sh[lane] : 0.f;
    if (wid == 0) {
#pragma unroll
        for (int o = 16; o > 0; o >>= 1) v += __shfl_down_sync(0xffffffffu, v, o);
        if (lane == 0) sh[0] = v;
    }
    __syncthreads();
    return sh[0];
}

__inline__ __device__ float siluf(float v) { return v / (1.f + expf(-v)); }

// ---------------- rmsnorm -> fp16 ----------------
__global__ void rmsnorm_h_kernel(const float* __restrict__ x, const float* __restrict__ w,
                                 __half* __restrict__ oh) {
    size_t row = blockIdx.x;
    const float* xr = x + row * DD;
    float ss = 0.f;
    for (int i = threadIdx.x; i < DD; i += blockDim.x) { float v = xr[i]; ss += v * v; }
    ss = blockReduceSum(ss);
    float inv = rsqrtf(ss / (float)DD + 1e-5f);
    for (int i = threadIdx.x; i < DD; i += blockDim.x)
        oh[row * DD + i] = __float2half(xr[i] * inv * w[i]);
}

// ---------------- transpose -> fp16 ----------------
__global__ void transpose_h_kernel(const float* __restrict__ src, int K, int N,
                                   __half* __restrict__ out, int Npad) {
    __shared__ float tile[32][33];
    int k0 = blockIdx.x * 32, n0 = blockIdx.y * 32;
#pragma unroll
    for (int i = 0; i < 4; i++) {
        int k = k0 + threadIdx.y + i * 8;
        int n = n0 + threadIdx.x;
        float v = (k < K && n < N) ? src[(size_t)k * N + n] : 0.f;
        tile[threadIdx.y + i * 8][threadIdx.x] = v;
    }
    __syncthreads();
#pragma unroll
    for (int i = 0; i < 4; i++) {
        int n = n0 + threadIdx.y + i * 8;
        int k = k0 + threadIdx.x;
        if (n < Npad && k < K)
            out[(size_t)n * K + k] = __float2half(tile[threadIdx.x][threadIdx.y + i * 8]);
    }
}

// ---------------- elementwise to fp16 ----------------
__global__ void tohalf_kernel(const float* __restrict__ src, __half* __restrict__ oh, size_t n) {
    size_t i = (size_t)blockIdx.x * blockDim.x + threadIdx.x;
    if (i >= n) return;
    oh[i] = __float2half(src[i]);
}

// ---------------- fp16 single-pass mma GEMM with column offset ----------------
#define TG_STAGE_BYTES 16384
#define TG_STAGES 4
#define TG_SMEM (TG_STAGES * TG_STAGE_BYTES)

__global__ __launch_bounds__(256, 2) void tgemm_kernel(const __half* __restrict__ A,
                                                       const __half* __restrict__ B,
                                                       float* __restrict__ C, int M, int N, int K,
                                                       int nbase) {
    extern __shared__ char smg[];
    uint32_t sb = s2u(smg);
    const int tid = threadIdx.x;
    const int wid = tid >> 5, lid = tid & 31;
    const int m0 = blockIdx.y * 128, n0 = blockIdx.x * 128 + nbase;
    const int wm = wid & 1, wn = wid >> 1;
    const int lr = lid & 15, lu = lid >> 4;
    const int NKC = K >> 5;

    const __half* gsrc[4];
    uint32_t dsto[4];
#pragma unroll
    for (int i = 0; i < 4; i++) {
        int q = tid + i * 256;
        int arr = q >> 9, idx = q & 511, row = idx >> 2, u = idx & 3;
        const __half* base = (arr == 0) ? A : B;
        int grow = ((arr == 0) ? m0 : n0) + row;
        gsrc[i] = base + (size_t)grow * K + u * 8;
        dsto[i] = (uint32_t)(arr * 8192 + row * 64 + ((u ^ (row & 3)) << 4));
    }

    auto issue = [&](int kc, int buf) {
        uint32_t sbuf = sb + buf * TG_STAGE_BYTES;
#pragma unroll
        for (int i = 0; i < 4; i++)
            asm volatile("cp.async.cg.shared.global [%0], [%1], 16;" ::
                         "r"(sbuf + dsto[i]), "l"((const void*)(gsrc[i] + (size_t)kc * 32))
                         : "memory");
    };

    float acc[4][4][4];
#pragma unroll
    for (int a = 0; a < 4; a++)
#pragma unroll
        for (int b = 0; b < 4; b++)
#pragma unroll
            for (int c = 0; c < 4; c++) acc[a][b][c] = 0.f;

    issue(0, 0);
    asm volatile("cp.async.commit_group;" ::: "memory");
    issue(1, 1);
    asm volatile("cp.async.commit_group;" ::: "memory");
    issue(2, 2);
    asm volatile("cp.async.commit_group;" ::: "memory");

    for (int kc = 0; kc < NKC; kc++) {
        asm volatile("cp.async.wait_group 2;" ::: "memory");
        __syncthreads();
        int nk = kc + 3;
        if (nk < NKC) issue(nk, nk & 3);
        asm volatile("cp.async.commit_group;" ::: "memory");

        uint32_t ab = sb + (kc & 3) * TG_STAGE_BYTES;
#pragma unroll
        for (int s = 0; s < 2; s++) {
            uint32_t af[4][4], bf[4][2];
#pragma unroll
            for (int mt = 0; mt < 4; mt++) {
                int r = wm * 64 + mt * 16 + lr;
                int u = 2 * s + lu;
                uint32_t ad = ab + r * 64 + ((u ^ (r & 3)) << 4);
                LDSM4(af[mt][0], af[mt][1], af[mt][2], af[mt][3], ad);
            }
#pragma unroll
            for (int p = 0; p < 2; p++) {
                int r = wn * 32 + p * 16 + lr;
                int u = 2 * s + lu;
                uint32_t bd = ab + 8192 + r * 64 + ((u ^ (r & 3)) << 4);
                uint32_t t0, t1, t2, t3;
                LDSM4(t0, t1, t2, t3, bd);
                bf[p * 2 + 0][0] = t0; bf[p * 2 + 0][1] = t2;
                bf[p * 2 + 1][0] = t1; bf[p * 2 + 1][1] = t3;
            }
#pragma unroll
            for (int mt = 0; mt < 4; mt++)
#pragma unroll
                for (int nt = 0; nt < 4; nt++)
                    MMA16816H(acc[mt][nt], af[mt], bf[nt]);
        }
    }

#pragma unroll
    for (int mt = 0; mt < 4; mt++) {
        int r = m0 + wm * 64 + mt * 16 + (lid >> 2);
#pragma unroll
        for (int nt = 0; nt < 4; nt++) {
            int n = n0 + wn * 32 + nt * 8 + (lid & 3) * 2;
            if (n < N) {
                *(float2*)&C[(size_t)r * N + n] = make_float2(acc[mt][nt][0], acc[mt][nt][1]);
                *(float2*)&C[(size_t)(r + 8) * N + n] = make_float2(acc[mt][nt][2], acc[mt][nt][3]);
            }
        }
    }
}

// ---------------- conv + silu ----------------
__global__ void conv_kernel(const float* __restrict__ zx, const float* __restrict__ cw,
                            const float* __restrict__ cb, float* __restrict__ out) {
    size_t idx = (size_t)blockIdx.x * blockDim.x + threadIdx.x;
    if (idx >= (size_t)BB * LL * CONVDIM) return;
    int c = idx % CONVDIM;
    size_t rest = idx / CONVDIM;
    int t = rest % LL;
    int b = rest / LL;
    float acc = cb[c];
#pragma unroll
    for (int k = 0; k < 4; k++) {
        int tt = t - 3 + k;
        if (tt >= 0)
            acc += zx[((size_t)b * LL + tt) * DPROJ + DIN + c] * cw[k * CONVDIM + c];
    }
    out[idx] = siluf(acc);
}

// ---------------- dt softplus + dA ----------------
__global__ void dtda_kernel(const float* __restrict__ zx, const float* __restrict__ dtb,
                            const float* __restrict__ alog, float* __restrict__ dtO,
                            float* __restrict__ dAO) {
    size_t idx = (size_t)blockIdx.x * blockDim.x + threadIdx.x;
    if (idx >= (size_t)BB * LL * NH) return;
    int h = idx % NH;
    size_t row = idx / NH;
    float raw = zx[row * DPROJ + (DPROJ - NH) + h] + dtb[h];
    float sp = (raw > 20.f) ? raw : log1pf(expf(raw));
    dtO[idx] = sp;
    dAO[idx] = expf(sp * (-expf(alog[h])));
}

// ---------------- SSM scan (unchanged, R9-validated) ----------------
#define SC_T 16
#define SC_NCH (LL / SC_T)

__global__ __launch_bounds__(512, 1) void scan_kernel(const float* __restrict__ conv,
                                                      const float* __restrict__ dtp,
                                                      const float* __restrict__ dAp,
                                                      float* __restrict__ yp0,
                                                      float* __restrict__ yp1) {
    const int s = blockIdx.x & 1;
    const int h = (blockIdx.x >> 1) & 31;
    const int b = blockIdx.x >> 6;
    float* __restrict__ yp = s ? yp1 : yp0;
    const int n0 = s * 64;
    const int tid = threadIdx.x;
    const int p = tid >> 3, ln = tid & 7;

    __shared__ __align__(16) float sB[3][SC_T][64];
    __shared__ __align__(16) float sC[3][SC_T][64];
    __shared__ __align__(16) float sx[3][SC_T][64];
    __shared__ float sdt[3][SC_T], sdA[3][SC_T];

    auto load = [&](int c, int st) {
#pragma unroll
        for (int q = tid; q < 800; q += 512) {
            if (q < 768) {
                int t = q / 48, k = q % 48;
                int arr = k >> 4, o = (k & 15) * 4;
                size_t g = (size_t)b * LL + (size_t)c * SC_T + t;
                const float* src;
                uint32_t d;
                if (arr == 0) { src = conv + g * CONVDIM + 2048 + n0 + o; d = s2u(&sB[st][t][o]); }
                else if (arr == 1) { src = conv + g * CONVDIM + 2176 + n0 + o; d = s2u(&sC[st][t][o]); }
                else { src = conv + g * CONVDIM + h * HD + o; d = s2u(&sx[st][t][o]); }
                asm volatile("cp.async.cg.shared.global [%0], [%1], 16;" :: "r"(d), "l"((const void*)src) : "memory");
            } else if (q < 784) {
                int t = q - 768;
                size_t g = (size_t)b * LL + (size_t)c * SC_T + t;
                uint32_t d = s2u(&sdt[st][t]);
                asm volatile("cp.async.ca.shared.global [%0], [%1], 4;" :: "r"(d), "l"((const void*)(dtp + g * NH + h)) : "memory");
            } else {
                int t = q - 784;
                size_t g = (size_t)b * LL + (size_t)c * SC_T + t;
                uint32_t d = s2u(&sdA[st][t]);
                asm volatile("cp.async.ca.shared.global [%0], [%1], 4;" :: "r"(d), "l"((const void*)(dAp + g * NH + h)) : "memory");
            }
        }
    };

    float S[8];
#pragma unroll
    for (int j = 0; j < 8; j++) S[j] = 0.f;

    load(0, 0);
    asm volatile("cp.async.commit_group;" ::: "memory");
    load(1, 1);
    asm volatile("cp.async.commit_group;" ::: "memory");

    for (int c = 0; c < SC_NCH; c++) {
        asm volatile("cp.async.wait_group 1;" ::: "memory");
        __syncthreads();
        if (c + 2 < SC_NCH) load(c + 2, (c + 2) % 3);
        asm volatile("cp.async.commit_group;" ::: "memory");

        const int st = c % 3;
        size_t gbase = ((size_t)b * LL + (size_t)c * SC_T) * DIN + h * HD + p;
#pragma unroll
        for (int t = 0; t < SC_T; t++) {
            float a = sdA[st][t];
            float dv = sdt[st][t];
            float xv = sx[st][t][p];
            float dtx = dv * xv;
            float4 b0 = *(float4*)&sB[st][t][ln * 8];
            float4 b1 = *(float4*)&sB[st][t][ln * 8 + 4];
            float4 c0 = *(float4*)&sC[st][t][ln * 8];
            float4 c1 = *(float4*)&sC[st][t][ln * 8 + 4];
            S[0] = fmaf(S[0], a, dtx * b0.x);
            S[1] = fmaf(S[1], a, dtx * b0.y);
            S[2] = fmaf(S[2], a, dtx * b0.z);
            S[3] = fmaf(S[3], a, dtx * b0.w);
            S[4] = fmaf(S[4], a, dtx * b1.x);
            S[5] = fmaf(S[5], a, dtx * b1.y);
            S[6] = fmaf(S[6], a, dtx * b1.z);
            S[7] = fmaf(S[7], a, dtx * b1.w);
            float part = S[0] * c0.x;
            part = fmaf(S[1], c0.y, part);
            part = fmaf(S[2], c0.z, part);
            part = fmaf(S[3], c0.w, part);
            part = fmaf(S[4], c1.x, part);
            part = fmaf(S[5], c1.y, part);
            part = fmaf(S[6], c1.z, part);
            part = fmaf(S[7], c1.w, part);
            part += __shfl_down_sync(0xffffffffu, part, 4, 8);
            part += __shfl_down_sync(0xffffffffu, part, 2, 8);
            part += __shfl_down_sync(0xffffffffu, part, 1, 8);
            if (ln == 0) yp[gbase + (size_t)t * DIN] = part;
        }
    }
}

// ---------------- gated rmsnorm -> fp16 ----------------
__global__ void gnorm_h_kernel(const float* __restrict__ y1, const float* __restrict__ y2,
                               const float* __restrict__ conv, const float* __restrict__ Dp,
                               const float* __restrict__ zx, const float* __restrict__ gw,
                               __half* __restrict__ oh) {
    size_t row = blockIdx.x;
    const float* zr = zx + row * DPROJ;
    float v[8];
    float ss = 0.f;
#pragma unroll
    for (int u = 0; u < 8; u++) {
        int i = threadIdx.x + u * 256;
        float xv = conv[row * CONVDIM + i];
        float yv = y1[row * DIN + i] + y2[row * DIN + i] + Dp[i >> 6] * xv;
        float z = zr[i];
        float val = yv * siluf(z);
        v[u] = val;
        ss += val * val;
    }
    ss = blockReduceSum(ss);
    float inv = rsqrtf(ss / (float)DIN + 1e-5f);
#pragma unroll
    for (int u = 0; u < 8; u++) {
        int i = threadIdx.x + u * 256;
        oh[row * DIN + i] = __float2half(v[u] * inv * gw[i]);
    }
}

// ---------------- cumsum passes (over Q = PQ[:,1024:2048]) ----------------
__global__ void chunk_sum_kernel(const float* __restrict__ PQ, float* __restrict__ cs) {
    int c = (blockIdx.x & 3) * 256 + threadIdx.x;
    int chunk = (blockIdx.x >> 2) & (NCHUNK - 1);
    int b = blockIdx.x >> 5;
    float s = 0.f;
    size_t base = ((size_t)b * LL + (size_t)chunk * CHL) * (2 * DD) + DD + c;
    for (int l = 0; l < CHL; l++) s += PQ[base + (size_t)l * (2 * DD)];
    cs[((size_t)b * NCHUNK + chunk) * DD + c] = s;
}

__global__ void scan_chunks_kernel(float* __restrict__ cs) {
    int i = blockIdx.x * blockDim.x + threadIdx.x;
    if (i >= BB * DD) return;
    int b = i / DD, c = i % DD;
    float acc = 0.f;
#pragma unroll
    for (int ch = 0; ch < NCHUNK; ch++) {
        size_t o = ((size_t)b * NCHUNK + ch) * DD + c;
        float v = cs[o];
        cs[o] = acc;
        acc += v;
    }
}

__global__ void final_kernel(const float* __restrict__ x, const float* __restrict__ PQ,
                             const float* __restrict__ R,
                             const float* __restrict__ cs, float* __restrict__ out) {
    int c = (blockIdx.x & 3) * 256 + threadIdx.x;
    int chunk = (blockIdx.x >> 2) & (NCHUNK - 1);
    int b = blockIdx.x >> 5;
    float acc = cs[((size_t)b * NCHUNK + chunk) * DD + c];
    size_t rbase = ((size_t)b * LL + (size_t)chunk * CHL) * DD + c;
    size_t pqbase = ((size_t)b * LL + (size_t)chunk * CHL) * (2 * DD) + c;
    for (int l = 0; l < CHL; l++) {
        size_t idx = rbase + (size_t)l * DD;
        size_t pqi = pqbase + (size_t)l * (2 * DD);
        acc += PQ[pqi + DD];
        out[idx] = x[idx] + PQ[pqi] + R[idx] + acc;
    }
}

// ---------------- launch ----------------
extern "C" void kernel_launch(void* const* d_in, const int* in_sizes, int n_in,
                              void* d_out, int out_size) {
    const float* x       = (const float*)d_in[0];
    const float* norm_w  = (const float*)d_in[1];
    const float* in_proj = (const float*)d_in[2];
    const float* conv_W  = (const float*)d_in[3];
    const float* conv_b  = (const float*)d_in[4];
    const float* dt_bias = (const float*)d_in[5];
    const float* A_log   = (const float*)d_in[6];
    const float* Dvec    = (const float*)d_in[7];
    const float* gnorm_w = (const float*)d_in[8];
    const float* zero_W  = (const float*)d_in[9];
    const float* one_W   = (const float*)d_in[10];
    const float* fusion  = (const float*)d_in[11];
    float* out = (float*)d_out;

    float *zx, *conv, *dt, *dA, *y1, *y2, *PQ, *R, *Wz, *Wc, *cs;
    __half *xnh, *Wpt, *Fzt, *Fot, *Fmt, *zw, *ow, *Wpq, *yh;
    cudaGetSymbolAddress((void**)&zx, g_zx);
    cudaGetSymbolAddress((void**)&conv, g_conv);
    cudaGetSymbolAddress((void**)&dt, g_dt);
    cudaGetSymbolAddress((void**)&dA, g_dA);
    cudaGetSymbolAddress((void**)&y1, g_y1);
    cudaGetSymbolAddress((void**)&y2, g_y2);
    cudaGetSymbolAddress((void**)&PQ, g_PQ);
    cudaGetSymbolAddress((void**)&R, g_R);
    cudaGetSymbolAddress((void**)&Wz, g_Wz);
    cudaGetSymbolAddress((void**)&Wc, g_Wc);
    cudaGetSymbolAddress((void**)&cs, g_cs);
    cudaGetSymbolAddress((void**)&xnh, g_xnh);
    cudaGetSymbolAddress((void**)&Wpt, g_Wpt);
    cudaGetSymbolAddress((void**)&Fzt, g_Fzt);
    cudaGetSymbolAddress((void**)&Fot, g_Fot);
    cudaGetSymbolAddress((void**)&Fmt, g_Fmt);
    cudaGetSymbolAddress((void**)&zw, g_zw);
    cudaGetSymbolAddress((void**)&ow, g_ow);
    cudaGetSymbolAddress((void**)&Wpq, g_Wpq);
    cudaGetSymbolAddress((void**)&yh, g_yh);

    const int M = BB * LL;
    cudaFuncSetAttribute(tgemm_kernel, cudaFuncAttributeMaxDynamicSharedMemorySize, TG_SMEM);

    // side stream + fork/join events (no device allocation; created per call)
    cudaStream_t s2;
    cudaEvent_t ev0, evA, evB;
    cudaStreamCreateWithFlags(&s2, cudaStreamNonBlocking);
    cudaEventCreateWithFlags(&ev0, cudaEventDisableTiming);
    cudaEventCreateWithFlags(&evA, cudaEventDisableTiming);
    cudaEventCreateWithFlags(&evB, cudaEventDisableTiming);

    dim3 tb(32, 8);

    // ---- main stream: prep everything both branches need ----
    rmsnorm_h_kernel<<<M, 256>>>(x, norm_w, xnh);
    transpose_h_kernel<<<dim3(DD / 32, NPADPROJ / 32), tb>>>(in_proj, DD, DPROJ, Wpt, NPADPROJ);
    transpose_h_kernel<<<dim3(DIN / 32, DD / 32), tb>>>(fusion, DIN, DD, Fmt, DD);
    cudaEventRecord(ev0, 0);   // xnh, Wpt, Fmt ready

    // ---- main: xBC+dt half of zx (cols 2048..4480), then conv/dtda ----
    tgemm_kernel<<<dim3((NPADPROJ - 2048) / 128, M / 128), 256, TG_SMEM>>>(xnh, Wpt, zx, M, DPROJ, DD, 2048);
    {
        size_t tot = (size_t)BB * LL * CONVDIM;
        conv_kernel<<<(unsigned)((tot + 255) / 256), 256>>>(zx, conv_W, conv_b, conv);
        size_t tot2 = (size_t)BB * LL * NH;
        dtda_kernel<<<(unsigned)((tot2 + 255) / 256), 256>>>(zx, dt_bias, A_log, dt, dA);
    }
    cudaEventRecord(evA, 0);   // conv, dt, dA ready

    // ---- side stream: z half of zx (concurrent with conv), then scan -> gnorm -> R ----
    cudaStreamWaitEvent(s2, ev0, 0);
    tgemm_kernel<<<dim3(2048 / 128, M / 128), 256, TG_SMEM, s2>>>(xnh, Wpt, zx, M, DPROJ, DD, 0);
    cudaStreamWaitEvent(s2, evA, 0);
    scan_kernel<<<128, 512, 0, s2>>>(conv, dt, dA, y1, y2);
    gnorm_h_kernel<<<M, 256, 0, s2>>>(y1, y2, conv, Dvec, zx, gnorm_w, yh);
    tgemm_kernel<<<dim3(8, M / 128), 256, TG_SMEM, s2>>>(yh, Fmt, R, M, DD, DIN, 0);
    cudaEventRecord(evB, s2);  // R ready

    // ---- main (concurrent with side stream): combines -> PQ -> cumsum prefix ----
    {
        size_t n = (size_t)DD * DIN;
        tohalf_kernel<<<(unsigned)((n + 255) / 256), 256>>>(zero_W, zw, n);
        tohalf_kernel<<<(unsigned)((n + 255) / 256), 256>>>(one_W, ow, n);
        transpose_h_kernel<<<dim3(DIN / 32, DD / 32), tb>>>(fusion + (size_t)DIN * DD, DIN, DD, Fzt, DD);
        transpose_h_kernel<<<dim3(DIN / 32, DD / 32), tb>>>(fusion + (size_t)2 * DIN * DD, DIN, DD, Fot, DD);
    }
    tgemm_kernel<<<dim3(8, 8), 256, TG_SMEM>>>(zw, Fzt, Wz, DD, DD, DIN, 0);
    tgemm_kernel<<<dim3(8, 8), 256, TG_SMEM>>>(ow, Fot, Wc, DD, DD, DIN, 0);
    transpose_h_kernel<<<dim3(DD / 32, DD / 32), tb>>>(Wz, DD, DD, Wpq, DD);
    transpose_h_kernel<<<dim3(DD / 32, DD / 32), tb>>>(Wc, DD, DD, Wpq + (size_t)DD * DD, DD);
    tgemm_kernel<<<dim3(16, M / 128), 256, TG_SMEM>>>(xnh, Wpq, PQ, M, 2 * DD, DD, 0);
    chunk_sum_kernel<<<BB * NCHUNK * 4, 256>>>(PQ, cs);
    scan_chunks_kernel<<<(BB * DD + 255) / 256, 256>>>(cs);

    // ---- join: final needs R (side) + PQ/cs (main) ----
    cudaStreamWaitEvent(0, evB, 0);
    final_kernel<<<BB * NCHUNK * 4, 256>>>(x, PQ, R, cs, out);

    // release handles (no device memory involved)
    cudaEventDestroy(ev0);
    cudaEventDestroy(evA);
    cudaEventDestroy(evB);
    cudaStreamDestroy(s2);
}